// round 6
// baseline (speedup 1.0000x reference)
#include <cuda_runtime.h>

#define HID 64
#define MAX_NODES 100000
#define MAX_EDGES 2000000
#define TE 128                 // edges per tile (16 ty-groups x 8 edges)
#define EDGE_SMEM ((64 * TE + 64 * 64) * 4)      // sDT + sC = 49152 B
#define NODE_SMEM ((3 * 4096 + 64 * 65) * 4)     // sW2,sA,sB + padded h tile

typedef unsigned long long ull;

__device__ float g_H[MAX_NODES * HID];
__device__ float g_P[MAX_NODES * HID];
__device__ float g_Q[MAX_NODES * HID];
__device__ int   g_U[MAX_EDGES];
__device__ int   g_V[MAX_EDGES];
__device__ int   g_is64;

// ---- packed f32x2 helpers ---------------------------------------------------
__device__ __forceinline__ ull pack2(float x, float y) {
    ull r; asm("mov.b64 %0, {%1, %2};" : "=l"(r) : "f"(x), "f"(y)); return r;
}
__device__ __forceinline__ void unpack2(ull v, float& x, float& y) {
    asm("mov.b64 {%0, %1}, %2;" : "=f"(x), "=f"(y) : "l"(v));
}
__device__ __forceinline__ ull ffma2(ull a, ull b, ull c) {
    ull r; asm("fma.rn.f32x2 %0, %1, %2, %3;" : "=l"(r) : "l"(a), "l"(b), "l"(c));
    return r;
}

// ---------------------------------------------------------------------------
// detect int64 vs int32 pairs (reads only first 2*n_edges words, in-bounds
// for both dtypes; int64 -> odd words all zero).
// ---------------------------------------------------------------------------
__global__ void detect_kernel(const int* __restrict__ w, int n_edges) {
    __shared__ int any_nz;
    if (threadIdx.x == 0) any_nz = 0;
    __syncthreads();
    int nz = 0;
    for (int j = threadIdx.x; j < 4096; j += blockDim.x) {
        long long idx = 1 + 2 * ((long long)j * (n_edges - 1) / 4096);
        if (idx < 2LL * n_edges) nz |= w[idx];
    }
    if (nz) atomicOr(&any_nz, 1);
    __syncthreads();
    if (threadIdx.x == 0) g_is64 = (any_nz == 0) ? 1 : 0;
}

__global__ void decode_kernel(const int* __restrict__ w, int n_edges) {
    int is64 = g_is64;
    int e = blockIdx.x * blockDim.x + threadIdx.x;
    if (e >= n_edges) return;
    int u, v;
    if (is64) { u = w[4LL * e]; v = w[4LL * e + 2]; }
    else      { u = w[2LL * e]; v = w[2LL * e + 1]; }
    g_U[e] = u;
    g_V[e] = v;
}

// ---------------------------------------------------------------------------
// Fused node kernel (persistent): H = relu(relu(X@W1+b1)@W2+b2) -> g_H;
// P = H@A + be1 -> g_P; Q = H@B -> g_Q.  16 q x 16 g, 4x4 register tiles,
// h tile stride 65 (conflict-free scalar k-reads).
// ---------------------------------------------------------------------------
__global__ __launch_bounds__(256) void node_kernel(
        const float* __restrict__ X,
        const float* __restrict__ W1, const float* __restrict__ b1,
        const float* __restrict__ W2, const float* __restrict__ b2,
        const float* __restrict__ We1, const float* __restrict__ be1,
        int n_nodes) {
    extern __shared__ float ns[];
    float* sW2 = ns;                 // [64][64]
    float* sA  = ns + 4096;          // [64][64]
    float* sB  = ns + 8192;          // [64][64]
    float* sh  = ns + 12288;         // [64][65] padded

    int tid = threadIdx.x;
    for (int i = tid; i < 4096; i += 256) {
        sW2[i] = W2[i];
        sA[i]  = We1[i];
        sB[i]  = We1[4096 + i];
    }

    int q = tid & 15;
    int g = tid >> 4;

    float w1r[4][4];
    #pragma unroll
    for (int c = 0; c < 4; c++) {
        float4 w = *(const float4*)&W1[c * HID + 4 * q];
        w1r[c][0] = w.x; w1r[c][1] = w.y; w1r[c][2] = w.z; w1r[c][3] = w.w;
    }
    float4 b1r  = *(const float4*)&b1[4 * q];
    float4 b2r  = *(const float4*)&b2[4 * q];
    float4 be1r = *(const float4*)&be1[4 * q];
    __syncthreads();

    for (int base = blockIdx.x * 64; base < n_nodes; base += gridDim.x * 64) {
        #pragma unroll
        for (int i = 0; i < 4; i++) {
            int node = base + 4 * g + i;
            float4 x = (node < n_nodes) ? *(const float4*)&X[(size_t)node * 4]
                                        : make_float4(0.f, 0.f, 0.f, 0.f);
            #pragma unroll
            for (int m = 0; m < 4; m++) {
                float h = ((const float*)&b1r)[m];
                h = fmaf(x.x, w1r[0][m], h);
                h = fmaf(x.y, w1r[1][m], h);
                h = fmaf(x.z, w1r[2][m], h);
                h = fmaf(x.w, w1r[3][m], h);
                sh[(4 * g + i) * 65 + 4 * q + m] = fmaxf(h, 0.f);
            }
        }
        __syncthreads();

        float acc[4][4];
        #pragma unroll
        for (int i = 0; i < 4; i++) {
            acc[i][0] = b2r.x; acc[i][1] = b2r.y;
            acc[i][2] = b2r.z; acc[i][3] = b2r.w;
        }
        #pragma unroll 8
        for (int k = 0; k < HID; k++) {
            float4 w = *(const float4*)&sW2[k * HID + 4 * q];
            #pragma unroll
            for (int i = 0; i < 4; i++) {
                float h = sh[(4 * g + i) * 65 + k];
                acc[i][0] = fmaf(h, w.x, acc[i][0]);
                acc[i][1] = fmaf(h, w.y, acc[i][1]);
                acc[i][2] = fmaf(h, w.z, acc[i][2]);
                acc[i][3] = fmaf(h, w.w, acc[i][3]);
            }
        }
        #pragma unroll
        for (int i = 0; i < 4; i++)
            #pragma unroll
            for (int m = 0; m < 4; m++)
                acc[i][m] = fmaxf(acc[i][m], 0.f);
        __syncthreads();

        #pragma unroll
        for (int i = 0; i < 4; i++) {
            #pragma unroll
            for (int m = 0; m < 4; m++)
                sh[(4 * g + i) * 65 + 4 * q + m] = acc[i][m];
            int node = base + 4 * g + i;
            if (node < n_nodes)
                *(float4*)&g_H[(size_t)node * HID + 4 * q] =
                    make_float4(acc[i][0], acc[i][1], acc[i][2], acc[i][3]);
        }
        __syncthreads();

        float pacc[4][4], qacc[4][4];
        #pragma unroll
        for (int i = 0; i < 4; i++) {
            pacc[i][0] = be1r.x; pacc[i][1] = be1r.y;
            pacc[i][2] = be1r.z; pacc[i][3] = be1r.w;
            qacc[i][0] = qacc[i][1] = qacc[i][2] = qacc[i][3] = 0.f;
        }
        #pragma unroll 4
        for (int k = 0; k < HID; k++) {
            float4 a4 = *(const float4*)&sA[k * HID + 4 * q];
            float4 b4 = *(const float4*)&sB[k * HID + 4 * q];
            #pragma unroll
            for (int i = 0; i < 4; i++) {
                float h = sh[(4 * g + i) * 65 + k];
                pacc[i][0] = fmaf(h, a4.x, pacc[i][0]);
                pacc[i][1] = fmaf(h, a4.y, pacc[i][1]);
                pacc[i][2] = fmaf(h, a4.z, pacc[i][2]);
                pacc[i][3] = fmaf(h, a4.w, pacc[i][3]);
                qacc[i][0] = fmaf(h, b4.x, qacc[i][0]);
                qacc[i][1] = fmaf(h, b4.y, qacc[i][1]);
                qacc[i][2] = fmaf(h, b4.z, qacc[i][2]);
                qacc[i][3] = fmaf(h, b4.w, qacc[i][3]);
            }
        }
        #pragma unroll
        for (int i = 0; i < 4; i++) {
            int node = base + 4 * g + i;
            if (node < n_nodes) {
                *(float4*)&g_P[(size_t)node * HID + 4 * q] =
                    make_float4(pacc[i][0], pacc[i][1], pacc[i][2], pacc[i][3]);
                *(float4*)&g_Q[(size_t)node * HID + 4 * q] =
                    make_float4(qacc[i][0], qacc[i][1], qacc[i][2], qacc[i][3]);
            }
        }
        __syncthreads();
    }
}

// ---------------------------------------------------------------------------
// Edge kernel (persistent): tiles of TE=128 edges.
// 128 thr = 8 tx (dims 8tx..8tx+7 as 4 f32x2) x 16 ty (8 edges each).
// acc = 32 ull (64 regs) -> 4 blocks/SM by RF; 48KB smem -> 4 blocks by smem.
// Manual k+1 prefetch double-buffer hides LDS latency.
// ---------------------------------------------------------------------------
__global__ __launch_bounds__(128, 4) void edge_kernel(
        const float* __restrict__ We1,
        const float* __restrict__ We2,
        const float* __restrict__ be2,
        float* __restrict__ out,
        int n_edges) {
    extern __shared__ float es[];
    float* sDT = es;                // [64][TE] transposed diff tile
    float* sC  = es + 64 * TE;      // [64][64] natural

    __shared__ int su[TE], sv[TE];

    int tid = threadIdx.x;
    int tx  = tid & 7;
    int ty  = tid >> 3;

    const float* C = We1 + 2 * HID * HID;
    for (int i = tid; i < HID * HID; i += 128) sC[i] = C[i];

    float w2r[8];
    {
        float4 wa = *(const float4*)&We2[8 * tx];
        float4 wb = *(const float4*)&We2[8 * tx + 4];
        w2r[0] = wa.x; w2r[1] = wa.y; w2r[2] = wa.z; w2r[3] = wa.w;
        w2r[4] = wb.x; w2r[5] = wb.y; w2r[6] = wb.z; w2r[7] = wb.w;
    }
    float bias = be2[0];

    int n_tiles = (n_edges + TE - 1) / TE;

    for (int tile = blockIdx.x; tile < n_tiles; tile += gridDim.x) {
        int e0 = tile * TE;

        __syncthreads();     // protect su/sv/sDT from previous tile
        {
            int e = e0 + tid;
            su[tid] = (e < n_edges) ? g_U[e] : 0;
            sv[tid] = (e < n_edges) ? g_V[e] : 0;
        }
        __syncthreads();

        // fill transposed diff tile: one edge per thread, coalesced STS
        {
            int e = tid;
            const float4* Hu = (const float4*)&g_H[(size_t)su[e] * HID];
            const float4* Hv = (const float4*)&g_H[(size_t)sv[e] * HID];
            #pragma unroll
            for (int c = 0; c < 16; c++) {
                float4 a = Hu[c];
                float4 b = Hv[c];
                sDT[(4 * c + 0) * TE + e] = fabsf(a.x - b.x);
                sDT[(4 * c + 1) * TE + e] = fabsf(a.y - b.y);
                sDT[(4 * c + 2) * TE + e] = fabsf(a.z - b.z);
                sDT[(4 * c + 3) * TE + e] = fabsf(a.w - b.w);
            }
        }

        // acc init: P[u]+Q[v] (LDGs overlap with fill; sync below)
        ull acc[8][4];
        #pragma unroll
        for (int i = 0; i < 8; i++) {
            int e = 8 * ty + i;
            const float* Pu = &g_P[(size_t)su[e] * HID + 8 * tx];
            const float* Qv = &g_Q[(size_t)sv[e] * HID + 8 * tx];
            float4 p0 = *(const float4*)&Pu[0];
            float4 p1 = *(const float4*)&Pu[4];
            float4 q0 = *(const float4*)&Qv[0];
            float4 q1 = *(const float4*)&Qv[4];
            acc[i][0] = pack2(p0.x + q0.x, p0.y + q0.y);
            acc[i][1] = pack2(p0.z + q0.z, p0.w + q0.w);
            acc[i][2] = pack2(p1.x + q1.x, p1.y + q1.y);
            acc[i][3] = pack2(p1.z + q1.z, p1.w + q1.w);
        }
        __syncthreads();     // sDT ready

        // FFMA2 mainloop with manual k+1 prefetch.
        // c loaded as ulonglong2 (ull pairs); row = 64 floats = 16 ulonglong2.
        const float* dB = sDT + 8 * ty;
        const ulonglong2* cB = (const ulonglong2*)sC + 2 * tx;

        float4 d0 = *(const float4*)(dB + 0);
        float4 d1 = *(const float4*)(dB + 4);
        ulonglong2 cA = cB[0];
        ulonglong2 cC = cB[1];

        #pragma unroll 4
        for (int k = 0; k < HID; k++) {
            int kn = (k < HID - 1) ? k + 1 : k;
            float4 nd0 = *(const float4*)(dB + kn * TE);
            float4 nd1 = *(const float4*)(dB + kn * TE + 4);
            ulonglong2 ncA = cB[kn * 16];          // FIXED: 16 ulonglong2 per row
            ulonglong2 ncC = cB[kn * 16 + 1];

            ull c0 = cA.x, c1 = cA.y, c2 = cC.x, c3 = cC.y;

            ull ds;
            ds = pack2(d0.x, d0.x);
            acc[0][0] = ffma2(ds, c0, acc[0][0]);
            acc[0][1] = ffma2(ds, c1, acc[0][1]);
            acc[0][2] = ffma2(ds, c2, acc[0][2]);
            acc[0][3] = ffma2(ds, c3, acc[0][3]);
            ds = pack2(d0.y, d0.y);
            acc[1][0] = ffma2(ds, c0, acc[1][0]);
            acc[1][1] = ffma2(ds, c1, acc[1][1]);
            acc[1][2] = ffma2(ds, c2, acc[1][2]);
            acc[1][3] = ffma2(ds, c3, acc[1][3]);
            ds = pack2(d0.z, d0.z);
            acc[2][0] = ffma2(ds, c0, acc[2][0]);
            acc[2][1] = ffma2(ds, c1, acc[2][1]);
            acc[2][2] = ffma2(ds, c2, acc[2][2]);
            acc[2][3] = ffma2(ds, c3, acc[2][3]);
            ds = pack2(d0.w, d0.w);
            acc[3][0] = ffma2(ds, c0, acc[3][0]);
            acc[3][1] = ffma2(ds, c1, acc[3][1]);
            acc[3][2] = ffma2(ds, c2, acc[3][2]);
            acc[3][3] = ffma2(ds, c3, acc[3][3]);
            ds = pack2(d1.x, d1.x);
            acc[4][0] = ffma2(ds, c0, acc[4][0]);
            acc[4][1] = ffma2(ds, c1, acc[4][1]);
            acc[4][2] = ffma2(ds, c2, acc[4][2]);
            acc[4][3] = ffma2(ds, c3, acc[4][3]);
            ds = pack2(d1.y, d1.y);
            acc[5][0] = ffma2(ds, c0, acc[5][0]);
            acc[5][1] = ffma2(ds, c1, acc[5][1]);
            acc[5][2] = ffma2(ds, c2, acc[5][2]);
            acc[5][3] = ffma2(ds, c3, acc[5][3]);
            ds = pack2(d1.z, d1.z);
            acc[6][0] = ffma2(ds, c0, acc[6][0]);
            acc[6][1] = ffma2(ds, c1, acc[6][1]);
            acc[6][2] = ffma2(ds, c2, acc[6][2]);
            acc[6][3] = ffma2(ds, c3, acc[6][3]);
            ds = pack2(d1.w, d1.w);
            acc[7][0] = ffma2(ds, c0, acc[7][0]);
            acc[7][1] = ffma2(ds, c1, acc[7][1]);
            acc[7][2] = ffma2(ds, c2, acc[7][2]);
            acc[7][3] = ffma2(ds, c3, acc[7][3]);

            d0 = nd0; d1 = nd1; cA = ncA; cC = ncC;
        }

        // epilogue: relu, dot We2 slice, reduce over 8 tx lanes
        #pragma unroll
        for (int i = 0; i < 8; i++) {
            float x0, x1, s;
            unpack2(acc[i][0], x0, x1);
            s = fmaxf(x0, 0.f) * w2r[0];
            s = fmaf(fmaxf(x1, 0.f), w2r[1], s);
            unpack2(acc[i][1], x0, x1);
            s = fmaf(fmaxf(x0, 0.f), w2r[2], s);
            s = fmaf(fmaxf(x1, 0.f), w2r[3], s);
            unpack2(acc[i][2], x0, x1);
            s = fmaf(fmaxf(x0, 0.f), w2r[4], s);
            s = fmaf(fmaxf(x1, 0.f), w2r[5], s);
            unpack2(acc[i][3], x0, x1);
            s = fmaf(fmaxf(x0, 0.f), w2r[6], s);
            s = fmaf(fmaxf(x1, 0.f), w2r[7], s);
            s += __shfl_xor_sync(0xffffffffu, s, 1);
            s += __shfl_xor_sync(0xffffffffu, s, 2);
            s += __shfl_xor_sync(0xffffffffu, s, 4);
            int e = e0 + 8 * ty + i;
            if (tx == 0 && e < n_edges) out[e] = s + bias;
        }
    }
}

// ---------------------------------------------------------------------------
extern "C" void kernel_launch(void* const* d_in, const int* in_sizes, int n_in,
                              void* d_out, int out_size) {
    const float* X     = (const float*)d_in[0];
    const int*   pairs = (const int*)d_in[1];
    const float* W1    = (const float*)d_in[2];
    const float* b1    = (const float*)d_in[3];
    const float* W2    = (const float*)d_in[4];
    const float* b2    = (const float*)d_in[5];
    const float* We1   = (const float*)d_in[6];
    const float* be1   = (const float*)d_in[7];
    const float* We2   = (const float*)d_in[8];
    const float* be2   = (const float*)d_in[9];
    float* out = (float*)d_out;

    int n_nodes = in_sizes[0] / 4;
    int n_edges = out_size;

    cudaFuncSetAttribute(node_kernel,
                         cudaFuncAttributeMaxDynamicSharedMemorySize, NODE_SMEM);
    cudaFuncSetAttribute(edge_kernel,
                         cudaFuncAttributeMaxDynamicSharedMemorySize, EDGE_SMEM);

    detect_kernel<<<1, 256>>>(pairs, n_edges);
    decode_kernel<<<(n_edges + 255) / 256, 256>>>(pairs, n_edges);
    node_kernel<<<444, 256, NODE_SMEM>>>(X, W1, b1, W2, b2, We1, be1, n_nodes);
    edge_kernel<<<592, 128, EDGE_SMEM>>>(We1, We2, be2, out, n_edges);
}

// round 7
// speedup vs baseline: 1.5682x; 1.5682x over previous
#include <cuda_runtime.h>

#define HID 64
#define MAX_NODES 100000
#define MAX_EDGES 2000000
#define NODE_SMEM ((3 * 4096 + 64 * 65) * 4)     // sW2,sA,sB + padded h tile

typedef unsigned long long ull;

__device__ float g_H[MAX_NODES * HID];
__device__ float g_P[MAX_NODES * HID];
__device__ float g_Q[MAX_NODES * HID];
__device__ int2  g_UV[MAX_EDGES];
__device__ int   g_is64;

// ---- packed f32x2 helpers ---------------------------------------------------
__device__ __forceinline__ ull pack2(float x, float y) {
    ull r; asm("mov.b64 %0, {%1, %2};" : "=l"(r) : "f"(x), "f"(y)); return r;
}
__device__ __forceinline__ void unpack2(ull v, float& x, float& y) {
    asm("mov.b64 {%0, %1}, %2;" : "=f"(x), "=f"(y) : "l"(v));
}
__device__ __forceinline__ ull ffma2(ull a, ull b, ull c) {
    ull r; asm("fma.rn.f32x2 %0, %1, %2, %3;" : "=l"(r) : "l"(a), "l"(b), "l"(c));
    return r;
}

// ---------------------------------------------------------------------------
// detect int64 vs int32 pairs (reads only first 2*n_edges words, in-bounds
// for both dtypes; int64 -> odd words all zero).
// ---------------------------------------------------------------------------
__global__ void detect_kernel(const int* __restrict__ w, int n_edges) {
    __shared__ int any_nz;
    if (threadIdx.x == 0) any_nz = 0;
    __syncthreads();
    int nz = 0;
    for (int j = threadIdx.x; j < 4096; j += blockDim.x) {
        long long idx = 1 + 2 * ((long long)j * (n_edges - 1) / 4096);
        if (idx < 2LL * n_edges) nz |= w[idx];
    }
    if (nz) atomicOr(&any_nz, 1);
    __syncthreads();
    if (threadIdx.x == 0) g_is64 = (any_nz == 0) ? 1 : 0;
}

__global__ void decode_kernel(const int* __restrict__ w, int n_edges) {
    int is64 = g_is64;
    int e = blockIdx.x * blockDim.x + threadIdx.x;
    if (e >= n_edges) return;
    int u, v;
    if (is64) { u = w[4LL * e]; v = w[4LL * e + 2]; }
    else      { u = w[2LL * e]; v = w[2LL * e + 1]; }
    g_UV[e] = make_int2(u, v);
}

// ---------------------------------------------------------------------------
// Fused node kernel (persistent): H = relu(relu(X@W1+b1)@W2+b2) -> g_H;
// P = H@A + be1 -> g_P; Q = H@B -> g_Q.  16 q x 16 g, 4x4 register tiles,
// h tile stride 65 (conflict-free scalar k-reads).
// ---------------------------------------------------------------------------
__global__ __launch_bounds__(256) void node_kernel(
        const float* __restrict__ X,
        const float* __restrict__ W1, const float* __restrict__ b1,
        const float* __restrict__ W2, const float* __restrict__ b2,
        const float* __restrict__ We1, const float* __restrict__ be1,
        int n_nodes) {
    extern __shared__ float ns[];
    float* sW2 = ns;                 // [64][64]
    float* sA  = ns + 4096;          // [64][64]
    float* sB  = ns + 8192;          // [64][64]
    float* sh  = ns + 12288;         // [64][65] padded

    int tid = threadIdx.x;
    for (int i = tid; i < 4096; i += 256) {
        sW2[i] = W2[i];
        sA[i]  = We1[i];
        sB[i]  = We1[4096 + i];
    }

    int q = tid & 15;
    int g = tid >> 4;

    float w1r[4][4];
    #pragma unroll
    for (int c = 0; c < 4; c++) {
        float4 w = *(const float4*)&W1[c * HID + 4 * q];
        w1r[c][0] = w.x; w1r[c][1] = w.y; w1r[c][2] = w.z; w1r[c][3] = w.w;
    }
    float4 b1r  = *(const float4*)&b1[4 * q];
    float4 b2r  = *(const float4*)&b2[4 * q];
    float4 be1r = *(const float4*)&be1[4 * q];
    __syncthreads();

    for (int base = blockIdx.x * 64; base < n_nodes; base += gridDim.x * 64) {
        #pragma unroll
        for (int i = 0; i < 4; i++) {
            int node = base + 4 * g + i;
            float4 x = (node < n_nodes) ? *(const float4*)&X[(size_t)node * 4]
                                        : make_float4(0.f, 0.f, 0.f, 0.f);
            #pragma unroll
            for (int m = 0; m < 4; m++) {
                float h = ((const float*)&b1r)[m];
                h = fmaf(x.x, w1r[0][m], h);
                h = fmaf(x.y, w1r[1][m], h);
                h = fmaf(x.z, w1r[2][m], h);
                h = fmaf(x.w, w1r[3][m], h);
                sh[(4 * g + i) * 65 + 4 * q + m] = fmaxf(h, 0.f);
            }
        }
        __syncthreads();

        float acc[4][4];
        #pragma unroll
        for (int i = 0; i < 4; i++) {
            acc[i][0] = b2r.x; acc[i][1] = b2r.y;
            acc[i][2] = b2r.z; acc[i][3] = b2r.w;
        }
        #pragma unroll 8
        for (int k = 0; k < HID; k++) {
            float4 w = *(const float4*)&sW2[k * HID + 4 * q];
            #pragma unroll
            for (int i = 0; i < 4; i++) {
                float h = sh[(4 * g + i) * 65 + k];
                acc[i][0] = fmaf(h, w.x, acc[i][0]);
                acc[i][1] = fmaf(h, w.y, acc[i][1]);
                acc[i][2] = fmaf(h, w.z, acc[i][2]);
                acc[i][3] = fmaf(h, w.w, acc[i][3]);
            }
        }
        #pragma unroll
        for (int i = 0; i < 4; i++)
            #pragma unroll
            for (int m = 0; m < 4; m++)
                acc[i][m] = fmaxf(acc[i][m], 0.f);
        __syncthreads();

        #pragma unroll
        for (int i = 0; i < 4; i++) {
            #pragma unroll
            for (int m = 0; m < 4; m++)
                sh[(4 * g + i) * 65 + 4 * q + m] = acc[i][m];
            int node = base + 4 * g + i;
            if (node < n_nodes)
                *(float4*)&g_H[(size_t)node * HID + 4 * q] =
                    make_float4(acc[i][0], acc[i][1], acc[i][2], acc[i][3]);
        }
        __syncthreads();

        float pacc[4][4], qacc[4][4];
        #pragma unroll
        for (int i = 0; i < 4; i++) {
            pacc[i][0] = be1r.x; pacc[i][1] = be1r.y;
            pacc[i][2] = be1r.z; pacc[i][3] = be1r.w;
            qacc[i][0] = qacc[i][1] = qacc[i][2] = qacc[i][3] = 0.f;
        }
        #pragma unroll 4
        for (int k = 0; k < HID; k++) {
            float4 a4 = *(const float4*)&sA[k * HID + 4 * q];
            float4 b4 = *(const float4*)&sB[k * HID + 4 * q];
            #pragma unroll
            for (int i = 0; i < 4; i++) {
                float h = sh[(4 * g + i) * 65 + k];
                pacc[i][0] = fmaf(h, a4.x, pacc[i][0]);
                pacc[i][1] = fmaf(h, a4.y, pacc[i][1]);
                pacc[i][2] = fmaf(h, a4.z, pacc[i][2]);
                pacc[i][3] = fmaf(h, a4.w, pacc[i][3]);
                qacc[i][0] = fmaf(h, b4.x, qacc[i][0]);
                qacc[i][1] = fmaf(h, b4.y, qacc[i][1]);
                qacc[i][2] = fmaf(h, b4.z, qacc[i][2]);
                qacc[i][3] = fmaf(h, b4.w, qacc[i][3]);
            }
        }
        #pragma unroll
        for (int i = 0; i < 4; i++) {
            int node = base + 4 * g + i;
            if (node < n_nodes) {
                *(float4*)&g_P[(size_t)node * HID + 4 * q] =
                    make_float4(pacc[i][0], pacc[i][1], pacc[i][2], pacc[i][3]);
                *(float4*)&g_Q[(size_t)node * HID + 4 * q] =
                    make_float4(qacc[i][0], qacc[i][1], qacc[i][2], qacc[i][3]);
            }
        }
        __syncthreads();
    }
}

// ---------------------------------------------------------------------------
// Edge kernel (persistent, warp-autonomous): each WARP owns 32-edge tiles.
// Lane (tx,ty): tx in 0..7 owns dims {4tx..4tx+3, 32+4tx..32+4tx+3};
// ty in 0..3 owns edges {8ty..8ty+7} of the warp tile.
// - All H/P/Q gathers are line-coalesced (8 lanes x 16B = one 128B line).
// - Diffs d[8][8] live in registers; mainloop broadcasts d[e][k] via shfl.
// - No shared diff tile, no __syncthreads in the tile loop.
// ---------------------------------------------------------------------------
__global__ __launch_bounds__(128, 3) void edge_kernel(
        const float* __restrict__ We1,
        const float* __restrict__ We2,
        const float* __restrict__ be2,
        float* __restrict__ out,
        int n_edges) {
    __shared__ float sC[HID * HID];    // C = We1 rows 128..191 (16 KB)

    int tid = threadIdx.x;
    int tx  = tid & 7;
    int ty  = (tid >> 3) & 3;
    int wid = tid >> 5;

    const float* C = We1 + 2 * HID * HID;
    for (int i = tid; i < HID * HID; i += 128) sC[i] = C[i];
    __syncthreads();

    // We2 slice for this lane's dims
    float4 w2a = *(const float4*)&We2[4 * tx];
    float4 w2b = *(const float4*)&We2[32 + 4 * tx];
    float bias = be2[0];

    int warp_global = blockIdx.x * 4 + wid;
    int n_wt = (n_edges + 31) >> 5;    // 32-edge warp tiles

    for (int t = warp_global; t < n_wt; t += gridDim.x * 4) {
        int ebase = t * 32 + 8 * ty;   // this lane's 8 edges

        // ---- gather: indices, H diffs (regs), acc init from P+Q ----
        float d[8][8];
        ull acc[8][4];
        #pragma unroll
        for (int i = 0; i < 8; i++) {
            int e = ebase + i;
            int2 uv = (e < n_edges) ? g_UV[e] : make_int2(0, 0);
            const float* Hu = &g_H[(size_t)uv.x * HID];
            const float* Hv = &g_H[(size_t)uv.y * HID];
            float4 a0 = *(const float4*)&Hu[4 * tx];
            float4 a1 = *(const float4*)&Hu[32 + 4 * tx];
            float4 b0 = *(const float4*)&Hv[4 * tx];
            float4 b1 = *(const float4*)&Hv[32 + 4 * tx];
            d[i][0] = fabsf(a0.x - b0.x);
            d[i][1] = fabsf(a0.y - b0.y);
            d[i][2] = fabsf(a0.z - b0.z);
            d[i][3] = fabsf(a0.w - b0.w);
            d[i][4] = fabsf(a1.x - b1.x);
            d[i][5] = fabsf(a1.y - b1.y);
            d[i][6] = fabsf(a1.z - b1.z);
            d[i][7] = fabsf(a1.w - b1.w);
            const float* Pu = &g_P[(size_t)uv.x * HID];
            const float* Qv = &g_Q[(size_t)uv.y * HID];
            float4 p0 = *(const float4*)&Pu[4 * tx];
            float4 p1 = *(const float4*)&Pu[32 + 4 * tx];
            float4 q0 = *(const float4*)&Qv[4 * tx];
            float4 q1 = *(const float4*)&Qv[32 + 4 * tx];
            acc[i][0] = pack2(p0.x + q0.x, p0.y + q0.y);
            acc[i][1] = pack2(p0.z + q0.z, p0.w + q0.w);
            acc[i][2] = pack2(p1.x + q1.x, p1.y + q1.y);
            acc[i][3] = pack2(p1.z + q1.z, p1.w + q1.w);
        }

        // ---- mainloop, k in [0,32): d source reg = d[i][k&3] ----
        #pragma unroll 4
        for (int k = 0; k < 32; k++) {
            int src = (ty << 3) + (k >> 2);           // owning lane in my ty-row
            ulonglong2 cA = *(const ulonglong2*)&sC[k * HID + 4 * tx];
            ulonglong2 cB = *(const ulonglong2*)&sC[k * HID + 32 + 4 * tx];
            #pragma unroll
            for (int i = 0; i < 8; i++) {
                float dv = __shfl_sync(0xffffffffu, d[i][k & 3], src);
                ull ds = pack2(dv, dv);
                acc[i][0] = ffma2(ds, cA.x, acc[i][0]);
                acc[i][1] = ffma2(ds, cA.y, acc[i][1]);
                acc[i][2] = ffma2(ds, cB.x, acc[i][2]);
                acc[i][3] = ffma2(ds, cB.y, acc[i][3]);
            }
        }
        // ---- mainloop, k in [32,64): d source reg = d[i][4+(k&3)] ----
        #pragma unroll 4
        for (int kk = 0; kk < 32; kk++) {
            int k = 32 + kk;
            int src = (ty << 3) + (kk >> 2);
            ulonglong2 cA = *(const ulonglong2*)&sC[k * HID + 4 * tx];
            ulonglong2 cB = *(const ulonglong2*)&sC[k * HID + 32 + 4 * tx];
            #pragma unroll
            for (int i = 0; i < 8; i++) {
                float dv = __shfl_sync(0xffffffffu, d[i][4 + (kk & 3)], src);
                ull ds = pack2(dv, dv);
                acc[i][0] = ffma2(ds, cA.x, acc[i][0]);
                acc[i][1] = ffma2(ds, cA.y, acc[i][1]);
                acc[i][2] = ffma2(ds, cB.x, acc[i][2]);
                acc[i][3] = ffma2(ds, cB.y, acc[i][3]);
            }
        }

        // ---- epilogue: relu, dot We2 slice, reduce over 8 tx lanes ----
        #pragma unroll
        for (int i = 0; i < 8; i++) {
            float x0, x1, s;
            unpack2(acc[i][0], x0, x1);
            s = fmaxf(x0, 0.f) * w2a.x;
            s = fmaf(fmaxf(x1, 0.f), w2a.y, s);
            unpack2(acc[i][1], x0, x1);
            s = fmaf(fmaxf(x0, 0.f), w2a.z, s);
            s = fmaf(fmaxf(x1, 0.f), w2a.w, s);
            unpack2(acc[i][2], x0, x1);
            s = fmaf(fmaxf(x0, 0.f), w2b.x, s);
            s = fmaf(fmaxf(x1, 0.f), w2b.y, s);
            unpack2(acc[i][3], x0, x1);
            s = fmaf(fmaxf(x0, 0.f), w2b.z, s);
            s = fmaf(fmaxf(x1, 0.f), w2b.w, s);
            s += __shfl_xor_sync(0xffffffffu, s, 1);
            s += __shfl_xor_sync(0xffffffffu, s, 2);
            s += __shfl_xor_sync(0xffffffffu, s, 4);
            int e = ebase + i;
            if (tx == 0 && e < n_edges) out[e] = s + bias;
        }
    }
}

// ---------------------------------------------------------------------------
extern "C" void kernel_launch(void* const* d_in, const int* in_sizes, int n_in,
                              void* d_out, int out_size) {
    const float* X     = (const float*)d_in[0];
    const int*   pairs = (const int*)d_in[1];
    const float* W1    = (const float*)d_in[2];
    const float* b1    = (const float*)d_in[3];
    const float* W2    = (const float*)d_in[4];
    const float* b2    = (const float*)d_in[5];
    const float* We1   = (const float*)d_in[6];
    const float* be1   = (const float*)d_in[7];
    const float* We2   = (const float*)d_in[8];
    const float* be2   = (const float*)d_in[9];
    float* out = (float*)d_out;

    int n_nodes = in_sizes[0] / 4;
    int n_edges = out_size;

    cudaFuncSetAttribute(node_kernel,
                         cudaFuncAttributeMaxDynamicSharedMemorySize, NODE_SMEM);

    detect_kernel<<<1, 256>>>(pairs, n_edges);
    decode_kernel<<<(n_edges + 255) / 256, 256>>>(pairs, n_edges);
    node_kernel<<<444, 256, NODE_SMEM>>>(X, W1, b1, W2, b2, We1, be1, n_nodes);
    edge_kernel<<<444, 128>>>(We1, We2, be2, out, n_edges);
}

// round 8
// speedup vs baseline: 2.2723x; 1.4491x over previous
#include <cuda_runtime.h>

#define HID 64
#define MAX_NODES 100000
#define MAX_EDGES 2000000
#define SD_STRIDE 68       // per-warp d/pq tile row stride (words)
#define SC_STRIDE 72       // C tile row stride (words): B-frag bank = 8c+r, conflict-free
#define NODE_SMEM ((3 * 4096 + 64 * 65) * 4)
#define EDGE_SMEM ((64 * SC_STRIDE + 64 + 4 * 32 * SD_STRIDE) * 4)

typedef unsigned int uint;

__device__ float g_H[MAX_NODES * HID];
__device__ float g_P[MAX_NODES * HID];
__device__ float g_Q[MAX_NODES * HID];
__device__ int2  g_UV[MAX_EDGES];
__device__ int   g_is64;

__device__ __forceinline__ uint to_tf32(float x) {
    uint r; asm("cvt.rna.tf32.f32 %0, %1;" : "=r"(r) : "f"(x)); return r;
}
__device__ __forceinline__ void mma_tf32(float4& d, const uint* a, uint b0, uint b1) {
    asm volatile(
        "mma.sync.aligned.m16n8k8.row.col.f32.tf32.tf32.f32 "
        "{%0,%1,%2,%3}, {%4,%5,%6,%7}, {%8,%9}, {%0,%1,%2,%3};"
        : "+f"(d.x), "+f"(d.y), "+f"(d.z), "+f"(d.w)
        : "r"(a[0]), "r"(a[1]), "r"(a[2]), "r"(a[3]), "r"(b0), "r"(b1));
}

// ---------------------------------------------------------------------------
// detect int64 vs int32 pairs (reads only first 2*n_edges words, in-bounds
// for both dtypes; int64 -> odd words all zero).
// ---------------------------------------------------------------------------
__global__ void detect_kernel(const int* __restrict__ w, int n_edges) {
    __shared__ int any_nz;
    if (threadIdx.x == 0) any_nz = 0;
    __syncthreads();
    int nz = 0;
    for (int j = threadIdx.x; j < 4096; j += blockDim.x) {
        long long idx = 1 + 2 * ((long long)j * (n_edges - 1) / 4096);
        if (idx < 2LL * n_edges) nz |= w[idx];
    }
    if (nz) atomicOr(&any_nz, 1);
    __syncthreads();
    if (threadIdx.x == 0) g_is64 = (any_nz == 0) ? 1 : 0;
}

__global__ void decode_kernel(const int* __restrict__ w, int n_edges) {
    int is64 = g_is64;
    int e = blockIdx.x * blockDim.x + threadIdx.x;
    if (e >= n_edges) return;
    int u, v;
    if (is64) { u = w[4LL * e]; v = w[4LL * e + 2]; }
    else      { u = w[2LL * e]; v = w[2LL * e + 1]; }
    g_UV[e] = make_int2(u, v);
}

// ---------------------------------------------------------------------------
// Fused node kernel (persistent): H = relu(relu(X@W1+b1)@W2+b2) -> g_H;
// P = H@A + be1 -> g_P; Q = H@B -> g_Q.
// ---------------------------------------------------------------------------
__global__ __launch_bounds__(256) void node_kernel(
        const float* __restrict__ X,
        const float* __restrict__ W1, const float* __restrict__ b1,
        const float* __restrict__ W2, const float* __restrict__ b2,
        const float* __restrict__ We1, const float* __restrict__ be1,
        int n_nodes) {
    extern __shared__ float ns[];
    float* sW2 = ns;
    float* sA  = ns + 4096;
    float* sB  = ns + 8192;
    float* sh  = ns + 12288;        // [64][65]

    int tid = threadIdx.x;
    for (int i = tid; i < 4096; i += 256) {
        sW2[i] = W2[i];
        sA[i]  = We1[i];
        sB[i]  = We1[4096 + i];
    }

    int q = tid & 15;
    int g = tid >> 4;

    float w1r[4][4];
    #pragma unroll
    for (int c = 0; c < 4; c++) {
        float4 w = *(const float4*)&W1[c * HID + 4 * q];
        w1r[c][0] = w.x; w1r[c][1] = w.y; w1r[c][2] = w.z; w1r[c][3] = w.w;
    }
    float4 b1r  = *(const float4*)&b1[4 * q];
    float4 b2r  = *(const float4*)&b2[4 * q];
    float4 be1r = *(const float4*)&be1[4 * q];
    __syncthreads();

    for (int base = blockIdx.x * 64; base < n_nodes; base += gridDim.x * 64) {
        #pragma unroll
        for (int i = 0; i < 4; i++) {
            int node = base + 4 * g + i;
            float4 x = (node < n_nodes) ? *(const float4*)&X[(size_t)node * 4]
                                        : make_float4(0.f, 0.f, 0.f, 0.f);
            #pragma unroll
            for (int m = 0; m < 4; m++) {
                float h = ((const float*)&b1r)[m];
                h = fmaf(x.x, w1r[0][m], h);
                h = fmaf(x.y, w1r[1][m], h);
                h = fmaf(x.z, w1r[2][m], h);
                h = fmaf(x.w, w1r[3][m], h);
                sh[(4 * g + i) * 65 + 4 * q + m] = fmaxf(h, 0.f);
            }
        }
        __syncthreads();

        float acc[4][4];
        #pragma unroll
        for (int i = 0; i < 4; i++) {
            acc[i][0] = b2r.x; acc[i][1] = b2r.y;
            acc[i][2] = b2r.z; acc[i][3] = b2r.w;
        }
        #pragma unroll 8
        for (int k = 0; k < HID; k++) {
            float4 w = *(const float4*)&sW2[k * HID + 4 * q];
            #pragma unroll
            for (int i = 0; i < 4; i++) {
                float h = sh[(4 * g + i) * 65 + k];
                acc[i][0] = fmaf(h, w.x, acc[i][0]);
                acc[i][1] = fmaf(h, w.y, acc[i][1]);
                acc[i][2] = fmaf(h, w.z, acc[i][2]);
                acc[i][3] = fmaf(h, w.w, acc[i][3]);
            }
        }
        #pragma unroll
        for (int i = 0; i < 4; i++)
            #pragma unroll
            for (int m = 0; m < 4; m++)
                acc[i][m] = fmaxf(acc[i][m], 0.f);
        __syncthreads();

        #pragma unroll
        for (int i = 0; i < 4; i++) {
            #pragma unroll
            for (int m = 0; m < 4; m++)
                sh[(4 * g + i) * 65 + 4 * q + m] = acc[i][m];
            int node = base + 4 * g + i;
            if (node < n_nodes)
                *(float4*)&g_H[(size_t)node * HID + 4 * q] =
                    make_float4(acc[i][0], acc[i][1], acc[i][2], acc[i][3]);
        }
        __syncthreads();

        float pacc[4][4], qacc[4][4];
        #pragma unroll
        for (int i = 0; i < 4; i++) {
            pacc[i][0] = be1r.x; pacc[i][1] = be1r.y;
            pacc[i][2] = be1r.z; pacc[i][3] = be1r.w;
            qacc[i][0] = qacc[i][1] = qacc[i][2] = qacc[i][3] = 0.f;
        }
        #pragma unroll 4
        for (int k = 0; k < HID; k++) {
            float4 a4 = *(const float4*)&sA[k * HID + 4 * q];
            float4 b4 = *(const float4*)&sB[k * HID + 4 * q];
            #pragma unroll
            for (int i = 0; i < 4; i++) {
                float h = sh[(4 * g + i) * 65 + k];
                pacc[i][0] = fmaf(h, a4.x, pacc[i][0]);
                pacc[i][1] = fmaf(h, a4.y, pacc[i][1]);
                pacc[i][2] = fmaf(h, a4.z, pacc[i][2]);
                pacc[i][3] = fmaf(h, a4.w, pacc[i][3]);
                qacc[i][0] = fmaf(h, b4.x, qacc[i][0]);
                qacc[i][1] = fmaf(h, b4.y, qacc[i][1]);
                qacc[i][2] = fmaf(h, b4.z, qacc[i][2]);
                qacc[i][3] = fmaf(h, b4.w, qacc[i][3]);
            }
        }
        #pragma unroll
        for (int i = 0; i < 4; i++) {
            int node = base + 4 * g + i;
            if (node < n_nodes) {
                *(float4*)&g_P[(size_t)node * HID + 4 * q] =
                    make_float4(pacc[i][0], pacc[i][1], pacc[i][2], pacc[i][3]);
                *(float4*)&g_Q[(size_t)node * HID + 4 * q] =
                    make_float4(qacc[i][0], qacc[i][1], qacc[i][2], qacc[i][3]);
            }
        }
        __syncthreads();
    }
}

// ---------------------------------------------------------------------------
// Edge kernel v8 (persistent, warp-autonomous, tf32 tensor cores).
// Warp tile = 32 edges. out[e][t] = relu(P[u]+Q[v] + D@C)[t] . We2 + be2.
// D@C (32x64x64) via 128x mma.m16n8k8 tf32; P+Q added fp32-exact pre-relu.
// Per-warp sD buffer: first holds tf32 |Hu-Hv|, then reused for fp32 P+Q.
// No __syncthreads in tile loop (warp-private buffers, __syncwarp only).
// ---------------------------------------------------------------------------
__global__ __launch_bounds__(128, 4) void edge_kernel(
        const float* __restrict__ We1,
        const float* __restrict__ We2,
        const float* __restrict__ be2,
        float* __restrict__ out,
        int n_edges) {
    extern __shared__ uint es8[];
    uint*  sC    = es8;                                   // [64][72] tf32 C
    float* sW2   = (float*)(es8 + 64 * SC_STRIDE);        // [64]
    uint*  sDall = es8 + 64 * SC_STRIDE + 64;             // 4 x [32][68]

    int tid  = threadIdx.x;
    int lane = tid & 31;
    int wid  = tid >> 5;
    uint*  sD  = sDall + wid * 32 * SD_STRIDE;
    float* sDf = (float*)sD;

    const float* C = We1 + 2 * HID * HID;
    for (int i = tid; i < HID * HID; i += 128) {
        int k = i >> 6, t = i & 63;
        sC[k * SC_STRIDE + t] = to_tf32(C[i]);
    }
    if (tid < HID) sW2[tid] = We2[tid];
    __syncthreads();

    int c   = lane & 3;      // mma thread-in-group
    int r   = lane >> 2;     // mma group id
    int txg = lane & 7;      // gather: dim group
    int tyg = lane >> 3;     // gather: edge row group (4 rows x 8 edges)
    float bias = be2[0];

    int n_wt = (n_edges + 31) >> 5;

    for (int t0 = blockIdx.x * 4 + wid; t0 < n_wt; t0 += gridDim.x * 4) {
        int ebase = t0 * 32;

        // ---- fill sD with tf32 |Hu - Hv| (coalesced gather, conflict-free STS)
        #pragma unroll
        for (int i = 0; i < 8; i++) {
            int e  = 8 * tyg + i;
            int eg = ebase + e;
            int2 uv = (eg < n_edges) ? g_UV[eg] : make_int2(0, 0);
            const float4* Hu = (const float4*)&g_H[(size_t)uv.x * HID];
            const float4* Hv = (const float4*)&g_H[(size_t)uv.y * HID];
            float4 a0 = Hu[txg],     b0 = Hv[txg];
            float4 a1 = Hu[8 + txg], b1 = Hv[8 + txg];
            uint4 s0, s1;
            s0.x = to_tf32(fabsf(a0.x - b0.x));
            s0.y = to_tf32(fabsf(a0.y - b0.y));
            s0.z = to_tf32(fabsf(a0.z - b0.z));
            s0.w = to_tf32(fabsf(a0.w - b0.w));
            s1.x = to_tf32(fabsf(a1.x - b1.x));
            s1.y = to_tf32(fabsf(a1.y - b1.y));
            s1.z = to_tf32(fabsf(a1.z - b1.z));
            s1.w = to_tf32(fabsf(a1.w - b1.w));
            *(uint4*)&sD[e * SD_STRIDE + 4 * txg]      = s0;
            *(uint4*)&sD[e * SD_STRIDE + 32 + 4 * txg] = s1;
        }
        __syncwarp();

        // ---- mma mainloop: acc[m][nt] (m16n8) over 8 k-tiles
        float4 acc[2][8];
        #pragma unroll
        for (int m = 0; m < 2; m++)
            #pragma unroll
            for (int nt = 0; nt < 8; nt++)
                acc[m][nt] = make_float4(0.f, 0.f, 0.f, 0.f);

        #pragma unroll
        for (int kt = 0; kt < 8; kt++) {
            uint a[2][4];
            #pragma unroll
            for (int m = 0; m < 2; m++) {
                a[m][0] = sD[(16 * m + r)     * SD_STRIDE + 8 * kt + c];
                a[m][1] = sD[(16 * m + 8 + r) * SD_STRIDE + 8 * kt + c];
                a[m][2] = sD[(16 * m + r)     * SD_STRIDE + 8 * kt + 4 + c];
                a[m][3] = sD[(16 * m + 8 + r) * SD_STRIDE + 8 * kt + 4 + c];
            }
            #pragma unroll
            for (int nt = 0; nt < 8; nt++) {
                uint b0 = sC[(8 * kt + c)     * SC_STRIDE + 8 * nt + r];
                uint b1 = sC[(8 * kt + 4 + c) * SC_STRIDE + 8 * nt + r];
                mma_tf32(acc[0][nt], a[0], b0, b1);
                mma_tf32(acc[1][nt], a[1], b0, b1);
            }
        }
        __syncwarp();

        // ---- overwrite sD with fp32 P[u]+Q[v] (same coalesced pattern)
        #pragma unroll
        for (int i = 0; i < 8; i++) {
            int e  = 8 * tyg + i;
            int eg = ebase + e;
            int2 uv = (eg < n_edges) ? g_UV[eg] : make_int2(0, 0);
            const float4* Pu = (const float4*)&g_P[(size_t)uv.x * HID];
            const float4* Qv = (const float4*)&g_Q[(size_t)uv.y * HID];
            float4 p0 = Pu[txg],     q0 = Qv[txg];
            float4 p1 = Pu[8 + txg], q1 = Qv[8 + txg];
            float4 s0 = make_float4(p0.x + q0.x, p0.y + q0.y, p0.z + q0.z, p0.w + q0.w);
            float4 s1 = make_float4(p1.x + q1.x, p1.y + q1.y, p1.z + q1.z, p1.w + q1.w);
            *(float4*)&sDf[e * SD_STRIDE + 4 * txg]      = s0;
            *(float4*)&sDf[e * SD_STRIDE + 32 + 4 * txg] = s1;
        }
        __syncwarp();

        // ---- epilogue: add P+Q, relu, dot We2, reduce over the 4-lane quad
        #pragma unroll
        for (int m = 0; m < 2; m++) {
            float sLo = 0.f, sHi = 0.f;
            #pragma unroll
            for (int nt = 0; nt < 8; nt++) {
                float w0 = sW2[8 * nt + 2 * c];
                float w1 = sW2[8 * nt + 2 * c + 1];
                float2 pqLo = *(const float2*)&sDf[(16 * m + r)     * SD_STRIDE + 8 * nt + 2 * c];
                float2 pqHi = *(const float2*)&sDf[(16 * m + 8 + r) * SD_STRIDE + 8 * nt + 2 * c];
                sLo = fmaf(fmaxf(acc[m][nt].x + pqLo.x, 0.f), w0, sLo);
                sLo = fmaf(fmaxf(acc[m][nt].y + pqLo.y, 0.f), w1, sLo);
                sHi = fmaf(fmaxf(acc[m][nt].z + pqHi.x, 0.f), w0, sHi);
                sHi = fmaf(fmaxf(acc[m][nt].w + pqHi.y, 0.f), w1, sHi);
            }
            sLo += __shfl_xor_sync(0xffffffffu, sLo, 1);
            sLo += __shfl_xor_sync(0xffffffffu, sLo, 2);
            sHi += __shfl_xor_sync(0xffffffffu, sHi, 1);
            sHi += __shfl_xor_sync(0xffffffffu, sHi, 2);
            if (c == 0) {
                int eLo = ebase + 16 * m + r;
                int eHi = eLo + 8;
                if (eLo < n_edges) out[eLo] = sLo + bias;
                if (eHi < n_edges) out[eHi] = sHi + bias;
            }
        }
        __syncwarp();   // epilogue reads done before next tile's fill STS
    }
}

// ---------------------------------------------------------------------------
extern "C" void kernel_launch(void* const* d_in, const int* in_sizes, int n_in,
                              void* d_out, int out_size) {
    const float* X     = (const float*)d_in[0];
    const int*   pairs = (const int*)d_in[1];
    const float* W1    = (const float*)d_in[2];
    const float* b1    = (const float*)d_in[3];
    const float* W2    = (const float*)d_in[4];
    const float* b2    = (const float*)d_in[5];
    const float* We1   = (const float*)d_in[6];
    const float* be1   = (const float*)d_in[7];
    const float* We2   = (const float*)d_in[8];
    const float* be2   = (const float*)d_in[9];
    float* out = (float*)d_out;

    int n_nodes = in_sizes[0] / 4;
    int n_edges = out_size;

    cudaFuncSetAttribute(node_kernel,
                         cudaFuncAttributeMaxDynamicSharedMemorySize, NODE_SMEM);
    cudaFuncSetAttribute(edge_kernel,
                         cudaFuncAttributeMaxDynamicSharedMemorySize, EDGE_SMEM);

    detect_kernel<<<1, 256>>>(pairs, n_edges);
    decode_kernel<<<(n_edges + 255) / 256, 256>>>(pairs, n_edges);
    node_kernel<<<444, 256, NODE_SMEM>>>(X, W1, b1, W2, b2, We1, be1, n_nodes);
    edge_kernel<<<444, 128, EDGE_SMEM>>>(We1, We2, be2, out, n_edges);
}

// round 9
// speedup vs baseline: 3.2347x; 1.4235x over previous
#include <cuda_runtime.h>
#include <cuda_fp16.h>

#define HID 64
#define MAX_NODES 100000
#define MAX_EDGES 2000000
#define SD_STRIDE 68
#define NODE_SMEM ((3 * 4096 + 64 * 65) * 4)
// sBf(4096) + sW2(64) + 4 warps x 32 x SD_STRIDE
#define EDGE_SMEM ((4096 + 64 + 4 * 32 * SD_STRIDE) * 4)

typedef unsigned int uint;
typedef unsigned long long ull;

__device__ __half g_Hh[MAX_NODES * HID];
__device__ __half g_Ph[MAX_NODES * HID];
__device__ __half g_Qh[MAX_NODES * HID];
__device__ int2   g_UV[MAX_EDGES];
__device__ int    g_is64;

__device__ __forceinline__ uint to_tf32(float x) {
    uint r; asm("cvt.rna.tf32.f32 %0, %1;" : "=r"(r) : "f"(x)); return r;
}
__device__ __forceinline__ void mma_tf32(float4& d, const uint* a, uint b0, uint b1) {
    asm volatile(
        "mma.sync.aligned.m16n8k8.row.col.f32.tf32.tf32.f32 "
        "{%0,%1,%2,%3}, {%4,%5,%6,%7}, {%8,%9}, {%0,%1,%2,%3};"
        : "+f"(d.x), "+f"(d.y), "+f"(d.z), "+f"(d.w)
        : "r"(a[0]), "r"(a[1]), "r"(a[2]), "r"(a[3]), "r"(b0), "r"(b1));
}
__device__ __forceinline__ ull pack2(float x, float y) {
    ull r; asm("mov.b64 %0, {%1, %2};" : "=l"(r) : "f"(x), "f"(y)); return r;
}
__device__ __forceinline__ void unpack2(ull v, float& x, float& y) {
    asm("mov.b64 {%0, %1}, %2;" : "=f"(x), "=f"(y) : "l"(v));
}
__device__ __forceinline__ ull ffma2(ull a, ull b, ull c) {
    ull r; asm("fma.rn.f32x2 %0, %1, %2, %3;" : "=l"(r) : "l"(a), "l"(b), "l"(c));
    return r;
}

// ---------------------------------------------------------------------------
__global__ void detect_kernel(const int* __restrict__ w, int n_edges) {
    __shared__ int any_nz;
    if (threadIdx.x == 0) any_nz = 0;
    __syncthreads();
    int nz = 0;
    for (int j = threadIdx.x; j < 4096; j += blockDim.x) {
        long long idx = 1 + 2 * ((long long)j * (n_edges - 1) / 4096);
        if (idx < 2LL * n_edges) nz |= w[idx];
    }
    if (nz) atomicOr(&any_nz, 1);
    __syncthreads();
    if (threadIdx.x == 0) g_is64 = (any_nz == 0) ? 1 : 0;
}

__global__ void decode_kernel(const int* __restrict__ w, int n_edges) {
    int is64 = g_is64;
    int e = blockIdx.x * blockDim.x + threadIdx.x;
    if (e >= n_edges) return;
    int u, v;
    if (is64) { u = w[4LL * e]; v = w[4LL * e + 2]; }
    else      { u = w[2LL * e]; v = w[2LL * e + 1]; }
    g_UV[e] = make_int2(u, v);
}

// ---------------------------------------------------------------------------
// Node kernel: H = relu(relu(X@W1+b1)@W2+b2); P = H@A+be1; Q = H@B.
// Outputs stored fp16. Phases 2/3 use packed fma.rn.f32x2 (identical rounding
// to scalar FFMA).
// ---------------------------------------------------------------------------
__global__ __launch_bounds__(256) void node_kernel(
        const float* __restrict__ X,
        const float* __restrict__ W1, const float* __restrict__ b1,
        const float* __restrict__ W2, const float* __restrict__ b2,
        const float* __restrict__ We1, const float* __restrict__ be1,
        int n_nodes) {
    extern __shared__ float ns[];
    float* sW2 = ns;
    float* sA  = ns + 4096;
    float* sB  = ns + 8192;
    float* sh  = ns + 12288;        // [64][65]

    int tid = threadIdx.x;
    for (int i = tid; i < 4096; i += 256) {
        sW2[i] = W2[i];
        sA[i]  = We1[i];
        sB[i]  = We1[4096 + i];
    }

    int q = tid & 15;
    int g = tid >> 4;

    float w1r[4][4];
    #pragma unroll
    for (int c = 0; c < 4; c++) {
        float4 w = *(const float4*)&W1[c * HID + 4 * q];
        w1r[c][0] = w.x; w1r[c][1] = w.y; w1r[c][2] = w.z; w1r[c][3] = w.w;
    }
    float4 b1r  = *(const float4*)&b1[4 * q];
    float4 b2r  = *(const float4*)&b2[4 * q];
    float4 be1r = *(const float4*)&be1[4 * q];
    __syncthreads();

    for (int base = blockIdx.x * 64; base < n_nodes; base += gridDim.x * 64) {
        // ---- phase 1: h1 = relu(X@W1+b1)
        #pragma unroll
        for (int i = 0; i < 4; i++) {
            int node = base + 4 * g + i;
            float4 x = (node < n_nodes) ? *(const float4*)&X[(size_t)node * 4]
                                        : make_float4(0.f, 0.f, 0.f, 0.f);
            #pragma unroll
            for (int m = 0; m < 4; m++) {
                float h = ((const float*)&b1r)[m];
                h = fmaf(x.x, w1r[0][m], h);
                h = fmaf(x.y, w1r[1][m], h);
                h = fmaf(x.z, w1r[2][m], h);
                h = fmaf(x.w, w1r[3][m], h);
                sh[(4 * g + i) * 65 + 4 * q + m] = fmaxf(h, 0.f);
            }
        }
        __syncthreads();

        // ---- phase 2: H = relu(h1@W2+b2)  (f32x2 packed)
        ull a0[4], a1[4];
        #pragma unroll
        for (int i = 0; i < 4; i++) {
            a0[i] = pack2(b2r.x, b2r.y);
            a1[i] = pack2(b2r.z, b2r.w);
        }
        #pragma unroll 8
        for (int k = 0; k < HID; k++) {
            ulonglong2 w = *(const ulonglong2*)&sW2[k * HID + 4 * q];
            #pragma unroll
            for (int i = 0; i < 4; i++) {
                float h = sh[(4 * g + i) * 65 + k];
                ull hs = pack2(h, h);
                a0[i] = ffma2(hs, w.x, a0[i]);
                a1[i] = ffma2(hs, w.y, a1[i]);
            }
        }
        float hv[4][4];
        #pragma unroll
        for (int i = 0; i < 4; i++) {
            unpack2(a0[i], hv[i][0], hv[i][1]);
            unpack2(a1[i], hv[i][2], hv[i][3]);
            #pragma unroll
            for (int m = 0; m < 4; m++) hv[i][m] = fmaxf(hv[i][m], 0.f);
        }
        __syncthreads();     // h1 reads done

        #pragma unroll
        for (int i = 0; i < 4; i++) {
            #pragma unroll
            for (int m = 0; m < 4; m++)
                sh[(4 * g + i) * 65 + 4 * q + m] = hv[i][m];
            int node = base + 4 * g + i;
            if (node < n_nodes) {
                __half2 h01 = __floats2half2_rn(hv[i][0], hv[i][1]);
                __half2 h23 = __floats2half2_rn(hv[i][2], hv[i][3]);
                uint2 st = make_uint2(*(uint*)&h01, *(uint*)&h23);
                *(uint2*)&g_Hh[(size_t)node * HID + 4 * q] = st;
            }
        }
        __syncthreads();

        // ---- phase 3: P = H@A + be1, Q = H@B  (f32x2 packed)
        ull p0[4], p1[4], q0[4], q1[4];
        #pragma unroll
        for (int i = 0; i < 4; i++) {
            p0[i] = pack2(be1r.x, be1r.y);
            p1[i] = pack2(be1r.z, be1r.w);
            q0[i] = pack2(0.f, 0.f);
            q1[i] = pack2(0.f, 0.f);
        }
        #pragma unroll 4
        for (int k = 0; k < HID; k++) {
            ulonglong2 av = *(const ulonglong2*)&sA[k * HID + 4 * q];
            ulonglong2 bv = *(const ulonglong2*)&sB[k * HID + 4 * q];
            #pragma unroll
            for (int i = 0; i < 4; i++) {
                float h = sh[(4 * g + i) * 65 + k];
                ull hs = pack2(h, h);
                p0[i] = ffma2(hs, av.x, p0[i]);
                p1[i] = ffma2(hs, av.y, p1[i]);
                q0[i] = ffma2(hs, bv.x, q0[i]);
                q1[i] = ffma2(hs, bv.y, q1[i]);
            }
        }
        #pragma unroll
        for (int i = 0; i < 4; i++) {
            int node = base + 4 * g + i;
            if (node < n_nodes) {
                float x0, x1, x2, x3;
                unpack2(p0[i], x0, x1); unpack2(p1[i], x2, x3);
                __half2 h01 = __floats2half2_rn(x0, x1);
                __half2 h23 = __floats2half2_rn(x2, x3);
                *(uint2*)&g_Ph[(size_t)node * HID + 4 * q] =
                    make_uint2(*(uint*)&h01, *(uint*)&h23);
                unpack2(q0[i], x0, x1); unpack2(q1[i], x2, x3);
                h01 = __floats2half2_rn(x0, x1);
                h23 = __floats2half2_rn(x2, x3);
                *(uint2*)&g_Qh[(size_t)node * HID + 4 * q] =
                    make_uint2(*(uint*)&h01, *(uint*)&h23);
            }
        }
        __syncthreads();
    }
}

// ---------------------------------------------------------------------------
// Edge kernel v9: fp16 gathers, tf32 MMA, fragment-major B in smem.
// Warp tile = 32 edges; warp-autonomous (no __syncthreads in tile loop).
// ---------------------------------------------------------------------------
__global__ __launch_bounds__(128, 4) void edge_kernel(
        const float* __restrict__ We1,
        const float* __restrict__ We2,
        const float* __restrict__ be2,
        float* __restrict__ out,
        int n_edges) {
    extern __shared__ uint es9[];
    uint*  sBf   = es9;                      // [8kt][4j][32lane][4] tf32 C frags
    float* sW2   = (float*)(es9 + 4096);     // [64]
    uint*  sDall = es9 + 4096 + 64;          // 4 x [32][SD_STRIDE]

    int tid  = threadIdx.x;
    int lane = tid & 31;
    int wid  = tid >> 5;
    uint*  sD  = sDall + wid * 32 * SD_STRIDE;
    float* sDf = (float*)sD;

    // Build fragment-major C: word ((kt*4+j)*32+lane)*4+s holds
    //   s=0: b0(nt=2j)   = C[8kt+c][8(2j)+r]
    //   s=1: b1(nt=2j)   = C[8kt+4+c][8(2j)+r]
    //   s=2: b0(nt=2j+1), s=3: b1(nt=2j+1)      (c=lane&3, r=lane>>2)
    const float* C = We1 + 2 * HID * HID;
    for (int idx = tid; idx < 4096; idx += 128) {
        int s  = idx & 3;
        int ln = (idx >> 2) & 31;
        int j  = (idx >> 7) & 3;
        int kt = idx >> 9;
        int c = ln & 3, r = ln >> 2;
        int nt = 2 * j + (s >> 1);
        int k  = 8 * kt + ((s & 1) ? 4 + c : c);
        int n  = 8 * nt + r;
        sBf[idx] = to_tf32(C[k * HID + n]);
    }
    if (tid < HID) sW2[tid] = We2[tid];
    __syncthreads();

    int c   = lane & 3;
    int r   = lane >> 2;
    int txg = lane & 7;
    int tyg = lane >> 3;
    float bias = be2[0];

    int n_wt = (n_edges + 31) >> 5;

    for (int t0 = blockIdx.x * 4 + wid; t0 < n_wt; t0 += gridDim.x * 4) {
        int ebase = t0 * 32;

        // ---- fill sD with tf32 |Hu-Hv| (one 128B line per node row)
        #pragma unroll
        for (int i = 0; i < 8; i++) {
            int e  = 8 * tyg + i;
            int eg = ebase + e;
            int2 uv = (eg < n_edges) ? g_UV[eg] : make_int2(0, 0);
            uint4 hu = *(const uint4*)&g_Hh[(size_t)uv.x * HID + 8 * txg];
            uint4 hv = *(const uint4*)&g_Hh[(size_t)uv.y * HID + 8 * txg];
            float2 u0 = __half22float2(*(__half2*)&hu.x);
            float2 u1 = __half22float2(*(__half2*)&hu.y);
            float2 u2 = __half22float2(*(__half2*)&hu.z);
            float2 u3 = __half22float2(*(__half2*)&hu.w);
            float2 v0 = __half22float2(*(__half2*)&hv.x);
            float2 v1 = __half22float2(*(__half2*)&hv.y);
            float2 v2 = __half22float2(*(__half2*)&hv.z);
            float2 v3 = __half22float2(*(__half2*)&hv.w);
            uint4 s0, s1;
            s0.x = to_tf32(fabsf(u0.x - v0.x));
            s0.y = to_tf32(fabsf(u0.y - v0.y));
            s0.z = to_tf32(fabsf(u1.x - v1.x));
            s0.w = to_tf32(fabsf(u1.y - v1.y));
            s1.x = to_tf32(fabsf(u2.x - v2.x));
            s1.y = to_tf32(fabsf(u2.y - v2.y));
            s1.z = to_tf32(fabsf(u3.x - v3.x));
            s1.w = to_tf32(fabsf(u3.y - v3.y));
            *(uint4*)&sD[e * SD_STRIDE + 8 * txg]     = s0;
            *(uint4*)&sD[e * SD_STRIDE + 8 * txg + 4] = s1;
        }
        __syncwarp();

        // ---- mma mainloop
        float4 acc[2][8];
        #pragma unroll
        for (int m = 0; m < 2; m++)
            #pragma unroll
            for (int nt = 0; nt < 8; nt++)
                acc[m][nt] = make_float4(0.f, 0.f, 0.f, 0.f);

        #pragma unroll
        for (int kt = 0; kt < 8; kt++) {
            uint a[2][4];
            #pragma unroll
            for (int m = 0; m < 2; m++) {
                a[m][0] = sD[(16 * m + r)     * SD_STRIDE + 8 * kt + c];
                a[m][1] = sD[(16 * m + 8 + r) * SD_STRIDE + 8 * kt + c];
                a[m][2] = sD[(16 * m + r)     * SD_STRIDE + 8 * kt + 4 + c];
                a[m][3] = sD[(16 * m + 8 + r) * SD_STRIDE + 8 * kt + 4 + c];
            }
            #pragma unroll
            for (int j = 0; j < 4; j++) {
                uint4 b = *(const uint4*)&sBf[((kt * 4 + j) * 32 + lane) * 4];
                mma_tf32(acc[0][2 * j],     a[0], b.x, b.y);
                mma_tf32(acc[1][2 * j],     a[1], b.x, b.y);
                mma_tf32(acc[0][2 * j + 1], a[0], b.z, b.w);
                mma_tf32(acc[1][2 * j + 1], a[1], b.z, b.w);
            }
        }
        __syncwarp();

        // ---- overwrite sD with fp32 P[u]+Q[v]
        #pragma unroll
        for (int i = 0; i < 8; i++) {
            int e  = 8 * tyg + i;
            int eg = ebase + e;
            int2 uv = (eg < n_edges) ? g_UV[eg] : make_int2(0, 0);
            uint4 pu = *(const uint4*)&g_Ph[(size_t)uv.x * HID + 8 * txg];
            uint4 qv = *(const uint4*)&g_Qh[(size_t)uv.y * HID + 8 * txg];
            float2 p0 = __half22float2(*(__half2*)&pu.x);
            float2 p1 = __half22float2(*(__half2*)&pu.y);
            float2 p2 = __half22float2(*(__half2*)&pu.z);
            float2 p3 = __half22float2(*(__half2*)&pu.w);
            float2 q0 = __half22float2(*(__half2*)&qv.x);
            float2 q1 = __half22float2(*(__half2*)&qv.y);
            float2 q2 = __half22float2(*(__half2*)&qv.z);
            float2 q3 = __half22float2(*(__half2*)&qv.w);
            float4 s0 = make_float4(p0.x + q0.x, p0.y + q0.y, p1.x + q1.x, p1.y + q1.y);
            float4 s1 = make_float4(p2.x + q2.x, p2.y + q2.y, p3.x + q3.x, p3.y + q3.y);
            *(float4*)&sDf[e * SD_STRIDE + 8 * txg]     = s0;
            *(float4*)&sDf[e * SD_STRIDE + 8 * txg + 4] = s1;
        }
        __syncwarp();

        // ---- epilogue: add P+Q, relu, dot We2, quad-reduce
        #pragma unroll
        for (int m = 0; m < 2; m++) {
            float sLo = 0.f, sHi = 0.f;
            #pragma unroll
            for (int nt = 0; nt < 8; nt++) {
                float w0 = sW2[8 * nt + 2 * c];
                float w1 = sW2[8 * nt + 2 * c + 1];
                float2 pqLo = *(const float2*)&sDf[(16 * m + r)     * SD_STRIDE + 8 * nt + 2 * c];
                float2 pqHi = *(const float2*)&sDf[(16 * m + 8 + r) * SD_STRIDE + 8 * nt + 2 * c];
                sLo = fmaf(fmaxf(acc[m][nt].x + pqLo.x, 0.f), w0, sLo);
                sLo = fmaf(fmaxf(acc[m][nt].y + pqLo.y, 0.f), w1, sLo);
                sHi = fmaf(fmaxf(acc[m][nt].z + pqHi.x, 0.f), w0, sHi);
                sHi = fmaf(fmaxf(acc[m][nt].w + pqHi.y, 0.f), w1, sHi);
            }
            sLo += __shfl_xor_sync(0xffffffffu, sLo, 1);
            sLo += __shfl_xor_sync(0xffffffffu, sLo, 2);
            sHi += __shfl_xor_sync(0xffffffffu, sHi, 1);
            sHi += __shfl_xor_sync(0xffffffffu, sHi, 2);
            if (c == 0) {
                int eLo = ebase + 16 * m + r;
                int eHi = eLo + 8;
                if (eLo < n_edges) out[eLo] = sLo + bias;
                if (eHi < n_edges) out[eHi] = sHi + bias;
            }
        }
        __syncwarp();   // epilogue reads done before next fill overwrites sD
    }
}

// ---------------------------------------------------------------------------
extern "C" void kernel_launch(void* const* d_in, const int* in_sizes, int n_in,
                              void* d_out, int out_size) {
    const float* X     = (const float*)d_in[0];
    const int*   pairs = (const int*)d_in[1];
    const float* W1    = (const float*)d_in[2];
    const float* b1    = (const float*)d_in[3];
    const float* W2    = (const float*)d_in[4];
    const float* b2    = (const float*)d_in[5];
    const float* We1   = (const float*)d_in[6];
    const float* be1   = (const float*)d_in[7];
    const float* We2   = (const float*)d_in[8];
    const float* be2   = (const float*)d_in[9];
    float* out = (float*)d_out;

    int n_nodes = in_sizes[0] / 4;
    int n_edges = out_size;

    cudaFuncSetAttribute(node_kernel,
                         cudaFuncAttributeMaxDynamicSharedMemorySize, NODE_SMEM);
    cudaFuncSetAttribute(edge_kernel,
                         cudaFuncAttributeMaxDynamicSharedMemorySize, EDGE_SMEM);

    detect_kernel<<<1, 256>>>(pairs, n_edges);
    decode_kernel<<<(n_edges + 255) / 256, 256>>>(pairs, n_edges);
    node_kernel<<<444, 256, NODE_SMEM>>>(X, W1, b1, W2, b2, We1, be1, n_nodes);
    edge_kernel<<<592, 128, EDGE_SMEM>>>(We1, We2, be2, out, n_edges);
}

// round 10
// speedup vs baseline: 4.9594x; 1.5332x over previous
#include <cuda_runtime.h>
#include <cuda_fp16.h>

#define HID 64
#define MAX_NODES 100000
#define MAX_EDGES 2000000
#define ST 36              // sD/sPQ row stride in uints (half2 units)
#define NODE_SMEM ((3 * 4096 + 64 * 65) * 4)
// sBf (2048 uints) + sW2 (64 f) + 4 warps x (sD + sPQ) (2 x 32 x ST uints)
#define EDGE_SMEM ((2048 + 64 + 4 * 2 * 32 * ST) * 4)

typedef unsigned int uint;
typedef unsigned long long ull;

__device__ __half g_Hh[MAX_NODES * HID];
__device__ __half g_Ph[MAX_NODES * HID];
__device__ __half g_Qh[MAX_NODES * HID];
__device__ int2   g_UV[MAX_EDGES];
__device__ int    g_is64;

__device__ __forceinline__ void mma_f16(float4& d, const uint* a, uint b0, uint b1) {
    asm volatile(
        "mma.sync.aligned.m16n8k16.row.col.f32.f16.f16.f32 "
        "{%0,%1,%2,%3}, {%4,%5,%6,%7}, {%8,%9}, {%0,%1,%2,%3};"
        : "+f"(d.x), "+f"(d.y), "+f"(d.z), "+f"(d.w)
        : "r"(a[0]), "r"(a[1]), "r"(a[2]), "r"(a[3]), "r"(b0), "r"(b1));
}
__device__ __forceinline__ ull pack2(float x, float y) {
    ull r; asm("mov.b64 %0, {%1, %2};" : "=l"(r) : "f"(x), "f"(y)); return r;
}
__device__ __forceinline__ void unpack2(ull v, float& x, float& y) {
    asm("mov.b64 {%0, %1}, %2;" : "=f"(x), "=f"(y) : "l"(v));
}
__device__ __forceinline__ ull ffma2(ull a, ull b, ull c) {
    ull r; asm("fma.rn.f32x2 %0, %1, %2, %3;" : "=l"(r) : "l"(a), "l"(b), "l"(c));
    return r;
}

// ---------------------------------------------------------------------------
__global__ void detect_kernel(const int* __restrict__ w, int n_edges) {
    __shared__ int any_nz;
    if (threadIdx.x == 0) any_nz = 0;
    __syncthreads();
    int nz = 0;
    for (int j = threadIdx.x; j < 4096; j += blockDim.x) {
        long long idx = 1 + 2 * ((long long)j * (n_edges - 1) / 4096);
        if (idx < 2LL * n_edges) nz |= w[idx];
    }
    if (nz) atomicOr(&any_nz, 1);
    __syncthreads();
    if (threadIdx.x == 0) g_is64 = (any_nz == 0) ? 1 : 0;
}

__global__ void decode_kernel(const int* __restrict__ w, int n_edges) {
    int is64 = g_is64;
    int e = blockIdx.x * blockDim.x + threadIdx.x;
    if (e >= n_edges) return;
    int u, v;
    if (is64) { u = w[4LL * e]; v = w[4LL * e + 2]; }
    else      { u = w[2LL * e]; v = w[2LL * e + 1]; }
    g_UV[e] = make_int2(u, v);
}

// ---------------------------------------------------------------------------
// Node kernel: H = relu(relu(X@W1+b1)@W2+b2); P = H@A+be1; Q = H@B.
// fp16 outputs; phases 2/3 packed f32x2.
// ---------------------------------------------------------------------------
__global__ __launch_bounds__(256) void node_kernel(
        const float* __restrict__ X,
        const float* __restrict__ W1, const float* __restrict__ b1,
        const float* __restrict__ W2, const float* __restrict__ b2,
        const float* __restrict__ We1, const float* __restrict__ be1,
        int n_nodes) {
    extern __shared__ float ns[];
    float* sW2 = ns;
    float* sA  = ns + 4096;
    float* sB  = ns + 8192;
    float* sh  = ns + 12288;        // [64][65]

    int tid = threadIdx.x;
    for (int i = tid; i < 4096; i += 256) {
        sW2[i] = W2[i];
        sA[i]  = We1[i];
        sB[i]  = We1[4096 + i];
    }

    int q = tid & 15;
    int g = tid >> 4;

    float w1r[4][4];
    #pragma unroll
    for (int c = 0; c < 4; c++) {
        float4 w = *(const float4*)&W1[c * HID + 4 * q];
        w1r[c][0] = w.x; w1r[c][1] = w.y; w1r[c][2] = w.z; w1r[c][3] = w.w;
    }
    float4 b1r  = *(const float4*)&b1[4 * q];
    float4 b2r  = *(const float4*)&b2[4 * q];
    float4 be1r = *(const float4*)&be1[4 * q];
    __syncthreads();

    for (int base = blockIdx.x * 64; base < n_nodes; base += gridDim.x * 64) {
        #pragma unroll
        for (int i = 0; i < 4; i++) {
            int node = base + 4 * g + i;
            float4 x = (node < n_nodes) ? *(const float4*)&X[(size_t)node * 4]
                                        : make_float4(0.f, 0.f, 0.f, 0.f);
            #pragma unroll
            for (int m = 0; m < 4; m++) {
                float h = ((const float*)&b1r)[m];
                h = fmaf(x.x, w1r[0][m], h);
                h = fmaf(x.y, w1r[1][m], h);
                h = fmaf(x.z, w1r[2][m], h);
                h = fmaf(x.w, w1r[3][m], h);
                sh[(4 * g + i) * 65 + 4 * q + m] = fmaxf(h, 0.f);
            }
        }
        __syncthreads();

        ull a0[4], a1[4];
        #pragma unroll
        for (int i = 0; i < 4; i++) {
            a0[i] = pack2(b2r.x, b2r.y);
            a1[i] = pack2(b2r.z, b2r.w);
        }
        #pragma unroll 8
        for (int k = 0; k < HID; k++) {
            ulonglong2 w = *(const ulonglong2*)&sW2[k * HID + 4 * q];
            #pragma unroll
            for (int i = 0; i < 4; i++) {
                float h = sh[(4 * g + i) * 65 + k];
                ull hs = pack2(h, h);
                a0[i] = ffma2(hs, w.x, a0[i]);
                a1[i] = ffma2(hs, w.y, a1[i]);
            }
        }
        float hv[4][4];
        #pragma unroll
        for (int i = 0; i < 4; i++) {
            unpack2(a0[i], hv[i][0], hv[i][1]);
            unpack2(a1[i], hv[i][2], hv[i][3]);
            #pragma unroll
            for (int m = 0; m < 4; m++) hv[i][m] = fmaxf(hv[i][m], 0.f);
        }
        __syncthreads();

        #pragma unroll
        for (int i = 0; i < 4; i++) {
            #pragma unroll
            for (int m = 0; m < 4; m++)
                sh[(4 * g + i) * 65 + 4 * q + m] = hv[i][m];
            int node = base + 4 * g + i;
            if (node < n_nodes) {
                __half2 h01 = __floats2half2_rn(hv[i][0], hv[i][1]);
                __half2 h23 = __floats2half2_rn(hv[i][2], hv[i][3]);
                *(uint2*)&g_Hh[(size_t)node * HID + 4 * q] =
                    make_uint2(*(uint*)&h01, *(uint*)&h23);
            }
        }
        __syncthreads();

        ull p0[4], p1[4], q0[4], q1[4];
        #pragma unroll
        for (int i = 0; i < 4; i++) {
            p0[i] = pack2(be1r.x, be1r.y);
            p1[i] = pack2(be1r.z, be1r.w);
            q0[i] = pack2(0.f, 0.f);
            q1[i] = pack2(0.f, 0.f);
        }
        #pragma unroll 4
        for (int k = 0; k < HID; k++) {
            ulonglong2 av = *(const ulonglong2*)&sA[k * HID + 4 * q];
            ulonglong2 bv = *(const ulonglong2*)&sB[k * HID + 4 * q];
            #pragma unroll
            for (int i = 0; i < 4; i++) {
                float h = sh[(4 * g + i) * 65 + k];
                ull hs = pack2(h, h);
                p0[i] = ffma2(hs, av.x, p0[i]);
                p1[i] = ffma2(hs, av.y, p1[i]);
                q0[i] = ffma2(hs, bv.x, q0[i]);
                q1[i] = ffma2(hs, bv.y, q1[i]);
            }
        }
        #pragma unroll
        for (int i = 0; i < 4; i++) {
            int node = base + 4 * g + i;
            if (node < n_nodes) {
                float x0, x1, x2, x3;
                unpack2(p0[i], x0, x1); unpack2(p1[i], x2, x3);
                __half2 h01 = __floats2half2_rn(x0, x1);
                __half2 h23 = __floats2half2_rn(x2, x3);
                *(uint2*)&g_Ph[(size_t)node * HID + 4 * q] =
                    make_uint2(*(uint*)&h01, *(uint*)&h23);
                unpack2(q0[i], x0, x1); unpack2(q1[i], x2, x3);
                h01 = __floats2half2_rn(x0, x1);
                h23 = __floats2half2_rn(x2, x3);
                *(uint2*)&g_Qh[(size_t)node * HID + 4 * q] =
                    make_uint2(*(uint*)&h01, *(uint*)&h23);
            }
        }
        __syncthreads();
    }
}

// ---------------------------------------------------------------------------
// Edge kernel v10: fp16 m16n8k16 MMA, fp16 PQ round-trip, PQ gather hoisted
// before the MMA loop so its latency is covered by tensor work.
// Warp tile = 32 edges; warp-autonomous.
// ---------------------------------------------------------------------------
__global__ __launch_bounds__(128, 4) void edge_kernel(
        const float* __restrict__ We1,
        const float* __restrict__ We2,
        const float* __restrict__ be2,
        float* __restrict__ out,
        int n_edges) {
    extern __shared__ uint es10[];
    uint*  sBf = es10;                       // [4kt][8nt][32lane][2] fp16 C frags
    float* sW2 = (float*)(es10 + 2048);      // [64]
    uint*  sDall = es10 + 2048 + 64;         // 4 warps x (sD[32][ST], sPQ[32][ST])

    int tid  = threadIdx.x;
    int lane = tid & 31;
    int wid  = tid >> 5;
    uint* sD  = sDall + wid * 2 * 32 * ST;
    uint* sPQ = sD + 32 * ST;

    // Build fp16 fragment-major C: for (kt,nt): b0 = (k=16kt+2c..+1, n=8nt+r),
    // b1 = (k=16kt+8+2c..+1, n=8nt+r). Stored [(kt*8+nt)*32+lane]*2 + {0,1}.
    const float* C = We1 + 2 * HID * HID;
    for (int idx = tid; idx < 2048; idx += 128) {
        int which = idx & 1;
        int ln    = (idx >> 1) & 31;
        int nt    = (idx >> 6) & 7;
        int kt    = idx >> 9;
        int c = ln & 3, r = ln >> 2;
        int k0 = 16 * kt + (which ? 8 : 0) + 2 * c;
        int n  = 8 * nt + r;
        __half2 h = __floats2half2_rn(C[k0 * HID + n], C[(k0 + 1) * HID + n]);
        sBf[idx] = *(uint*)&h;
    }
    if (tid < HID) sW2[tid] = We2[tid];
    __syncthreads();

    int c   = lane & 3;
    int r   = lane >> 2;
    int txg = lane & 7;      // dim group (8 dims = 4 uints)
    int tyg = lane >> 3;     // edge row group
    float bias = be2[0];

    int n_wt = (n_edges + 31) >> 5;

    for (int t0 = blockIdx.x * 4 + wid; t0 < n_wt; t0 += gridDim.x * 4) {
        int ebase = t0 * 32;

        // ---- gather H diffs -> sD (fp16), P+Q -> sPQ (fp16); coalesced ----
        #pragma unroll
        for (int i = 0; i < 8; i++) {
            int e  = 8 * tyg + i;
            int eg = ebase + e;
            int2 uv = (eg < n_edges) ? g_UV[eg] : make_int2(0, 0);
            uint4 hu = *(const uint4*)&g_Hh[(size_t)uv.x * HID + 8 * txg];
            uint4 hv = *(const uint4*)&g_Hh[(size_t)uv.y * HID + 8 * txg];
            uint4 pu = *(const uint4*)&g_Ph[(size_t)uv.x * HID + 8 * txg];
            uint4 qv = *(const uint4*)&g_Qh[(size_t)uv.y * HID + 8 * txg];
            uint4 d, s;
            __half2 t;
            t = __habs2(__hsub2(*(__half2*)&hu.x, *(__half2*)&hv.x)); d.x = *(uint*)&t;
            t = __habs2(__hsub2(*(__half2*)&hu.y, *(__half2*)&hv.y)); d.y = *(uint*)&t;
            t = __habs2(__hsub2(*(__half2*)&hu.z, *(__half2*)&hv.z)); d.z = *(uint*)&t;
            t = __habs2(__hsub2(*(__half2*)&hu.w, *(__half2*)&hv.w)); d.w = *(uint*)&t;
            t = __hadd2(*(__half2*)&pu.x, *(__half2*)&qv.x); s.x = *(uint*)&t;
            t = __hadd2(*(__half2*)&pu.y, *(__half2*)&qv.y); s.y = *(uint*)&t;
            t = __hadd2(*(__half2*)&pu.z, *(__half2*)&qv.z); s.z = *(uint*)&t;
            t = __hadd2(*(__half2*)&pu.w, *(__half2*)&qv.w); s.w = *(uint*)&t;
            *(uint4*)&sD[e * ST + 4 * txg]  = d;
            *(uint4*)&sPQ[e * ST + 4 * txg] = s;
        }
        __syncwarp();

        // ---- fp16 mma mainloop: 4 k-tiles of 16 ----
        float4 acc[2][8];
        #pragma unroll
        for (int m = 0; m < 2; m++)
            #pragma unroll
            for (int nt = 0; nt < 8; nt++)
                acc[m][nt] = make_float4(0.f, 0.f, 0.f, 0.f);

        #pragma unroll
        for (int kt = 0; kt < 4; kt++) {
            uint a[2][4];
            #pragma unroll
            for (int m = 0; m < 2; m++) {
                a[m][0] = sD[(16 * m + r)     * ST + 8 * kt + c];
                a[m][1] = sD[(16 * m + 8 + r) * ST + 8 * kt + c];
                a[m][2] = sD[(16 * m + r)     * ST + 8 * kt + 4 + c];
                a[m][3] = sD[(16 * m + 8 + r) * ST + 8 * kt + 4 + c];
            }
            #pragma unroll
            for (int nt = 0; nt < 8; nt++) {
                uint2 b = *(const uint2*)&sBf[((kt * 8 + nt) * 32 + lane) * 2];
                mma_f16(acc[0][nt], a[0], b.x, b.y);
                mma_f16(acc[1][nt], a[1], b.x, b.y);
            }
        }

        // ---- epilogue: + PQ (fp16 smem), relu, dot We2, quad-reduce ----
        #pragma unroll
        for (int m = 0; m < 2; m++) {
            float sLo = 0.f, sHi = 0.f;
            #pragma unroll
            for (int nt = 0; nt < 8; nt++) {
                float w0 = sW2[8 * nt + 2 * c];
                float w1 = sW2[8 * nt + 2 * c + 1];
                uint pqL = sPQ[(16 * m + r)     * ST + 4 * nt + c];
                uint pqH = sPQ[(16 * m + 8 + r) * ST + 4 * nt + c];
                float2 lo = __half22float2(*(__half2*)&pqL);
                float2 hi = __half22float2(*(__half2*)&pqH);
                sLo = fmaf(fmaxf(acc[m][nt].x + lo.x, 0.f), w0, sLo);
                sLo = fmaf(fmaxf(acc[m][nt].y + lo.y, 0.f), w1, sLo);
                sHi = fmaf(fmaxf(acc[m][nt].z + hi.x, 0.f), w0, sHi);
                sHi = fmaf(fmaxf(acc[m][nt].w + hi.y, 0.f), w1, sHi);
            }
            sLo += __shfl_xor_sync(0xffffffffu, sLo, 1);
            sLo += __shfl_xor_sync(0xffffffffu, sLo, 2);
            sHi += __shfl_xor_sync(0xffffffffu, sHi, 1);
            sHi += __shfl_xor_sync(0xffffffffu, sHi, 2);
            if (c == 0) {
                int eLo = ebase + 16 * m + r;
                int eHi = eLo + 8;
                if (eLo < n_edges) out[eLo] = sLo + bias;
                if (eHi < n_edges) out[eHi] = sHi + bias;
            }
        }
        __syncwarp();   // all reads done before next tile overwrites sD/sPQ
    }
}

// ---------------------------------------------------------------------------
extern "C" void kernel_launch(void* const* d_in, const int* in_sizes, int n_in,
                              void* d_out, int out_size) {
    const float* X     = (const float*)d_in[0];
    const int*   pairs = (const int*)d_in[1];
    const float* W1    = (const float*)d_in[2];
    const float* b1    = (const float*)d_in[3];
    const float* W2    = (const float*)d_in[4];
    const float* b2    = (const float*)d_in[5];
    const float* We1   = (const float*)d_in[6];
    const float* be1   = (const float*)d_in[7];
    const float* We2   = (const float*)d_in[8];
    const float* be2   = (const float*)d_in[9];
    float* out = (float*)d_out;

    int n_nodes = in_sizes[0] / 4;
    int n_edges = out_size;

    cudaFuncSetAttribute(node_kernel,
                         cudaFuncAttributeMaxDynamicSharedMemorySize, NODE_SMEM);
    cudaFuncSetAttribute(edge_kernel,
                         cudaFuncAttributeMaxDynamicSharedMemorySize, EDGE_SMEM);

    detect_kernel<<<1, 256>>>(pairs, n_edges);
    decode_kernel<<<(n_edges + 255) / 256, 256>>>(pairs, n_edges);
    node_kernel<<<444, 256, NODE_SMEM>>>(X, W1, b1, W2, b2, We1, be1, n_nodes);
    edge_kernel<<<592, 128, EDGE_SMEM>>>(We1, We2, be2, out, n_edges);
}

// round 11
// speedup vs baseline: 5.1336x; 1.0351x over previous
#include <cuda_runtime.h>
#include <cuda_fp16.h>

#define HID 64
#define MAX_NODES 100000
#define MAX_EDGES 2000000
#define ST 36              // sD/sPQ row stride in uints
#define NODE_SMEM ((3 * 4096 + 128 * 68) * 4)
#define EDGE_SMEM ((64 + 4 * 2 * 32 * ST) * 4)

typedef unsigned int uint;
typedef unsigned long long ull;

__device__ __half g_Hh[MAX_NODES * HID];
__device__ __half g_Ph[MAX_NODES * HID];
__device__ __half g_Qh[MAX_NODES * HID];
__device__ int2   g_UV[MAX_EDGES];
__device__ int    g_is64;

__device__ __forceinline__ void mma_f16(float4& d, const uint* a, uint b0, uint b1) {
    asm volatile(
        "mma.sync.aligned.m16n8k16.row.col.f32.f16.f16.f32 "
        "{%0,%1,%2,%3}, {%4,%5,%6,%7}, {%8,%9}, {%0,%1,%2,%3};"
        : "+f"(d.x), "+f"(d.y), "+f"(d.z), "+f"(d.w)
        : "r"(a[0]), "r"(a[1]), "r"(a[2]), "r"(a[3]), "r"(b0), "r"(b1));
}
__device__ __forceinline__ ull pack2(float x, float y) {
    ull r; asm("mov.b64 %0, {%1, %2};" : "=l"(r) : "f"(x), "f"(y)); return r;
}
__device__ __forceinline__ void unpack2(ull v, float& x, float& y) {
    asm("mov.b64 {%0, %1}, %2;" : "=f"(x), "=f"(y) : "l"(v));
}
__device__ __forceinline__ ull ffma2(ull a, ull b, ull c) {
    ull r; asm("fma.rn.f32x2 %0, %1, %2, %3;" : "=l"(r) : "l"(a), "l"(b), "l"(c));
    return r;
}

// ---------------------------------------------------------------------------
__global__ void detect_kernel(const int* __restrict__ w, int n_edges) {
    __shared__ int any_nz;
    if (threadIdx.x == 0) any_nz = 0;
    __syncthreads();
    int nz = 0;
    for (int j = threadIdx.x; j < 4096; j += blockDim.x) {
        long long idx = 1 + 2 * ((long long)j * (n_edges - 1) / 4096);
        if (idx < 2LL * n_edges) nz |= w[idx];
    }
    if (nz) atomicOr(&any_nz, 1);
    __syncthreads();
    if (threadIdx.x == 0) g_is64 = (any_nz == 0) ? 1 : 0;
}

__global__ void decode_kernel(const int* __restrict__ w, int n_edges) {
    int is64 = g_is64;
    int e = blockIdx.x * blockDim.x + threadIdx.x;
    if (e >= n_edges) return;
    int u, v;
    if (is64) { u = w[4LL * e]; v = w[4LL * e + 2]; }
    else      { u = w[2LL * e]; v = w[2LL * e + 1]; }
    g_UV[e] = make_int2(u, v);
}

// ---------------------------------------------------------------------------
// Node kernel v11: 128-node tiles, 8 nodes x 4 dims per thread, k-step-2
// inner loops (float2 h loads) to halve L1 wavefronts per FLOP.
// ---------------------------------------------------------------------------
__global__ __launch_bounds__(256, 2) void node_kernel(
        const float* __restrict__ X,
        const float* __restrict__ W1, const float* __restrict__ b1,
        const float* __restrict__ W2, const float* __restrict__ b2,
        const float* __restrict__ We1, const float* __restrict__ be1,
        int n_nodes) {
    extern __shared__ float ns[];
    float* sW2 = ns;
    float* sA  = ns + 4096;
    float* sB  = ns + 8192;
    float* sh  = ns + 12288;        // [128][68]

    int tid = threadIdx.x;
    for (int i = tid; i < 4096; i += 256) {
        sW2[i] = W2[i];
        sA[i]  = We1[i];
        sB[i]  = We1[4096 + i];
    }

    int q = tid & 15;
    int g = tid >> 4;

    float w1r[4][4];
    #pragma unroll
    for (int c = 0; c < 4; c++) {
        float4 w = *(const float4*)&W1[c * HID + 4 * q];
        w1r[c][0] = w.x; w1r[c][1] = w.y; w1r[c][2] = w.z; w1r[c][3] = w.w;
    }
    float4 b1r  = *(const float4*)&b1[4 * q];
    float4 b2r  = *(const float4*)&b2[4 * q];
    float4 be1r = *(const float4*)&be1[4 * q];
    __syncthreads();

    for (int base = blockIdx.x * 128; base < n_nodes; base += gridDim.x * 128) {
        // ---- phase 1: h1 = relu(X@W1+b1)
        #pragma unroll
        for (int i = 0; i < 8; i++) {
            int node = base + 8 * g + i;
            float4 x = (node < n_nodes) ? *(const float4*)&X[(size_t)node * 4]
                                        : make_float4(0.f, 0.f, 0.f, 0.f);
            #pragma unroll
            for (int m = 0; m < 4; m++) {
                float h = ((const float*)&b1r)[m];
                h = fmaf(x.x, w1r[0][m], h);
                h = fmaf(x.y, w1r[1][m], h);
                h = fmaf(x.z, w1r[2][m], h);
                h = fmaf(x.w, w1r[3][m], h);
                sh[(8 * g + i) * 68 + 4 * q + m] = fmaxf(h, 0.f);
            }
        }
        __syncthreads();

        // ---- phase 2: H = relu(h1@W2+b2)
        ull a0[8], a1[8];
        #pragma unroll
        for (int i = 0; i < 8; i++) {
            a0[i] = pack2(b2r.x, b2r.y);
            a1[i] = pack2(b2r.z, b2r.w);
        }
        #pragma unroll 4
        for (int k = 0; k < HID; k += 2) {
            ulonglong2 w0 = *(const ulonglong2*)&sW2[k * HID + 4 * q];
            ulonglong2 w1 = *(const ulonglong2*)&sW2[(k + 1) * HID + 4 * q];
            #pragma unroll
            for (int i = 0; i < 8; i++) {
                float2 h2 = *(const float2*)&sh[(8 * g + i) * 68 + k];
                ull hs0 = pack2(h2.x, h2.x);
                ull hs1 = pack2(h2.y, h2.y);
                a0[i] = ffma2(hs0, w0.x, a0[i]);
                a1[i] = ffma2(hs0, w0.y, a1[i]);
                a0[i] = ffma2(hs1, w1.x, a0[i]);
                a1[i] = ffma2(hs1, w1.y, a1[i]);
            }
        }
        float hv[8][4];
        #pragma unroll
        for (int i = 0; i < 8; i++) {
            unpack2(a0[i], hv[i][0], hv[i][1]);
            unpack2(a1[i], hv[i][2], hv[i][3]);
            #pragma unroll
            for (int m = 0; m < 4; m++) hv[i][m] = fmaxf(hv[i][m], 0.f);
        }
        __syncthreads();       // h1 reads done

        #pragma unroll
        for (int i = 0; i < 8; i++) {
            #pragma unroll
            for (int m = 0; m < 4; m++)
                sh[(8 * g + i) * 68 + 4 * q + m] = hv[i][m];
            int node = base + 8 * g + i;
            if (node < n_nodes) {
                __half2 h01 = __floats2half2_rn(hv[i][0], hv[i][1]);
                __half2 h23 = __floats2half2_rn(hv[i][2], hv[i][3]);
                *(uint2*)&g_Hh[(size_t)node * HID + 4 * q] =
                    make_uint2(*(uint*)&h01, *(uint*)&h23);
            }
        }
        __syncthreads();

        // ---- phase 3: P = H@A + be1, Q = H@B
        ull p0[8], p1[8], q0[8], q1[8];
        #pragma unroll
        for (int i = 0; i < 8; i++) {
            p0[i] = pack2(be1r.x, be1r.y);
            p1[i] = pack2(be1r.z, be1r.w);
            q0[i] = pack2(0.f, 0.f);
            q1[i] = pack2(0.f, 0.f);
        }
        #pragma unroll 2
        for (int k = 0; k < HID; k += 2) {
            ulonglong2 av0 = *(const ulonglong2*)&sA[k * HID + 4 * q];
            ulonglong2 av1 = *(const ulonglong2*)&sA[(k + 1) * HID + 4 * q];
            ulonglong2 bv0 = *(const ulonglong2*)&sB[k * HID + 4 * q];
            ulonglong2 bv1 = *(const ulonglong2*)&sB[(k + 1) * HID + 4 * q];
            #pragma unroll
            for (int i = 0; i < 8; i++) {
                float2 h2 = *(const float2*)&sh[(8 * g + i) * 68 + k];
                ull hs0 = pack2(h2.x, h2.x);
                ull hs1 = pack2(h2.y, h2.y);
                p0[i] = ffma2(hs0, av0.x, p0[i]);
                p1[i] = ffma2(hs0, av0.y, p1[i]);
                q0[i] = ffma2(hs0, bv0.x, q0[i]);
                q1[i] = ffma2(hs0, bv0.y, q1[i]);
                p0[i] = ffma2(hs1, av1.x, p0[i]);
                p1[i] = ffma2(hs1, av1.y, p1[i]);
                q0[i] = ffma2(hs1, bv1.x, q0[i]);
                q1[i] = ffma2(hs1, bv1.y, q1[i]);
            }
        }
        #pragma unroll
        for (int i = 0; i < 8; i++) {
            int node = base + 8 * g + i;
            if (node < n_nodes) {
                float x0, x1, x2, x3;
                unpack2(p0[i], x0, x1); unpack2(p1[i], x2, x3);
                __half2 h01 = __floats2half2_rn(x0, x1);
                __half2 h23 = __floats2half2_rn(x2, x3);
                *(uint2*)&g_Ph[(size_t)node * HID + 4 * q] =
                    make_uint2(*(uint*)&h01, *(uint*)&h23);
                unpack2(q0[i], x0, x1); unpack2(q1[i], x2, x3);
                h01 = __floats2half2_rn(x0, x1);
                h23 = __floats2half2_rn(x2, x3);
                *(uint2*)&g_Qh[(size_t)node * HID + 4 * q] =
                    make_uint2(*(uint*)&h01, *(uint*)&h23);
            }
        }
        __syncthreads();
    }
}

// ---------------------------------------------------------------------------
// Edge kernel v11: fp16 MMA with B(C) fragments persisted in REGISTERS
// (loaded once from gmem) -> -64 L1 wavefronts and -32 LDS per tile.
// ---------------------------------------------------------------------------
__global__ __launch_bounds__(128, 3) void edge_kernel(
        const float* __restrict__ We1,
        const float* __restrict__ We2,
        const float* __restrict__ be2,
        float* __restrict__ out,
        int n_edges) {
    extern __shared__ uint es11[];
    float* sW2 = (float*)es11;               // [64]
    uint*  sDall = es11 + 64;                // 4 warps x (sD[32][ST], sPQ[32][ST])

    int tid  = threadIdx.x;
    int lane = tid & 31;
    int wid  = tid >> 5;
    uint* sD  = sDall + wid * 2 * 32 * ST;
    uint* sPQ = sD + 32 * ST;

    int c = lane & 3;
    int r = lane >> 2;

    // B(C) fragments -> registers, loaded once. For (kt,nt):
    //   b0 covers k=16kt+2c..+1, b1 covers k=16kt+8+2c..+1, col n=8nt+r.
    const float* C = We1 + 2 * HID * HID;
    uint breg[4][8][2];
    #pragma unroll
    for (int kt = 0; kt < 4; kt++)
        #pragma unroll
        for (int nt = 0; nt < 8; nt++) {
            int n  = 8 * nt + r;
            int k0 = 16 * kt + 2 * c;
            int k1 = 16 * kt + 8 + 2 * c;
            __half2 h0 = __floats2half2_rn(C[k0 * HID + n], C[(k0 + 1) * HID + n]);
            __half2 h1 = __floats2half2_rn(C[k1 * HID + n], C[(k1 + 1) * HID + n]);
            breg[kt][nt][0] = *(uint*)&h0;
            breg[kt][nt][1] = *(uint*)&h1;
        }
    if (tid < HID) sW2[tid] = We2[tid];
    __syncthreads();

    int txg = lane & 7;
    int tyg = lane >> 3;
    float bias = be2[0];

    int n_wt = (n_edges + 31) >> 5;

    for (int t0 = blockIdx.x * 4 + wid; t0 < n_wt; t0 += gridDim.x * 4) {
        int ebase = t0 * 32;

        // ---- gather H diffs -> sD, P+Q -> sPQ (fp16, coalesced) ----
        #pragma unroll
        for (int i = 0; i < 8; i++) {
            int e  = 8 * tyg + i;
            int eg = ebase + e;
            int2 uv = (eg < n_edges) ? g_UV[eg] : make_int2(0, 0);
            uint4 hu = *(const uint4*)&g_Hh[(size_t)uv.x * HID + 8 * txg];
            uint4 hv = *(const uint4*)&g_Hh[(size_t)uv.y * HID + 8 * txg];
            uint4 pu = *(const uint4*)&g_Ph[(size_t)uv.x * HID + 8 * txg];
            uint4 qv = *(const uint4*)&g_Qh[(size_t)uv.y * HID + 8 * txg];
            uint4 d, s;
            __half2 t;
            t = __habs2(__hsub2(*(__half2*)&hu.x, *(__half2*)&hv.x)); d.x = *(uint*)&t;
            t = __habs2(__hsub2(*(__half2*)&hu.y, *(__half2*)&hv.y)); d.y = *(uint*)&t;
            t = __habs2(__hsub2(*(__half2*)&hu.z, *(__half2*)&hv.z)); d.z = *(uint*)&t;
            t = __habs2(__hsub2(*(__half2*)&hu.w, *(__half2*)&hv.w)); d.w = *(uint*)&t;
            t = __hadd2(*(__half2*)&pu.x, *(__half2*)&qv.x); s.x = *(uint*)&t;
            t = __hadd2(*(__half2*)&pu.y, *(__half2*)&qv.y); s.y = *(uint*)&t;
            t = __hadd2(*(__half2*)&pu.z, *(__half2*)&qv.z); s.z = *(uint*)&t;
            t = __hadd2(*(__half2*)&pu.w, *(__half2*)&qv.w); s.w = *(uint*)&t;
            *(uint4*)&sD[e * ST + 4 * txg]  = d;
            *(uint4*)&sPQ[e * ST + 4 * txg] = s;
        }
        __syncwarp();

        // ---- fp16 mma mainloop ----
        float4 acc[2][8];
        #pragma unroll
        for (int m = 0; m < 2; m++)
            #pragma unroll
            for (int nt = 0; nt < 8; nt++)
                acc[m][nt] = make_float4(0.f, 0.f, 0.f, 0.f);

        #pragma unroll
        for (int kt = 0; kt < 4; kt++) {
            uint a[2][4];
            #pragma unroll
            for (int m = 0; m < 2; m++) {
                a[m][0] = sD[(16 * m + r)     * ST + 8 * kt + c];
                a[m][1] = sD[(16 * m + 8 + r) * ST + 8 * kt + c];
                a[m][2] = sD[(16 * m + r)     * ST + 8 * kt + 4 + c];
                a[m][3] = sD[(16 * m + 8 + r) * ST + 8 * kt + 4 + c];
            }
            #pragma unroll
            for (int nt = 0; nt < 8; nt++) {
                mma_f16(acc[0][nt], a[0], breg[kt][nt][0], breg[kt][nt][1]);
                mma_f16(acc[1][nt], a[1], breg[kt][nt][0], breg[kt][nt][1]);
            }
        }

        // ---- epilogue: + PQ, relu, dot We2, quad-reduce ----
        #pragma unroll
        for (int m = 0; m < 2; m++) {
            float sLo = 0.f, sHi = 0.f;
            #pragma unroll
            for (int nt = 0; nt < 8; nt++) {
                float w0 = sW2[8 * nt + 2 * c];
                float w1 = sW2[8 * nt + 2 * c + 1];
                uint pqL = sPQ[(16 * m + r)     * ST + 4 * nt + c];
                uint pqH = sPQ[(16 * m + 8 + r) * ST + 4 * nt + c];
                float2 lo = __half22float2(*(__half2*)&pqL);
                float2 hi = __half22float2(*(__half2*)&pqH);
                sLo = fmaf(fmaxf(acc[m][nt].x + lo.x, 0.f), w0, sLo);
                sLo = fmaf(fmaxf(acc[m][nt].y + lo.y, 0.f), w1, sLo);
                sHi = fmaf(fmaxf(acc[m][nt].z + hi.x, 0.f), w0, sHi);
                sHi = fmaf(fmaxf(acc[m][nt].w + hi.y, 0.f), w1, sHi);
            }
            sLo += __shfl_xor_sync(0xffffffffu, sLo, 1);
            sLo += __shfl_xor_sync(0xffffffffu, sLo, 2);
            sHi += __shfl_xor_sync(0xffffffffu, sHi, 1);
            sHi += __shfl_xor_sync(0xffffffffu, sHi, 2);
            if (c == 0) {
                int eLo = ebase + 16 * m + r;
                int eHi = eLo + 8;
                if (eLo < n_edges) out[eLo] = sLo + bias;
                if (eHi < n_edges) out[eHi] = sHi + bias;
            }
        }
        __syncwarp();   // all reads done before next tile overwrites sD/sPQ
    }
}

// ---------------------------------------------------------------------------
extern "C" void kernel_launch(void* const* d_in, const int* in_sizes, int n_in,
                              void* d_out, int out_size) {
    const float* X     = (const float*)d_in[0];
    const int*   pairs = (const int*)d_in[1];
    const float* W1    = (const float*)d_in[2];
    const float* b1    = (const float*)d_in[3];
    const float* W2    = (const float*)d_in[4];
    const float* b2    = (const float*)d_in[5];
    const float* We1   = (const float*)d_in[6];
    const float* be1   = (const float*)d_in[7];
    const float* We2   = (const float*)d_in[8];
    const float* be2   = (const float*)d_in[9];
    float* out = (float*)d_out;

    int n_nodes = in_sizes[0] / 4;
    int n_edges = out_size;

    cudaFuncSetAttribute(node_kernel,
                         cudaFuncAttributeMaxDynamicSharedMemorySize, NODE_SMEM);
    cudaFuncSetAttribute(edge_kernel,
                         cudaFuncAttributeMaxDynamicSharedMemorySize, EDGE_SMEM);

    detect_kernel<<<1, 256>>>(pairs, n_edges);
    decode_kernel<<<(n_edges + 255) / 256, 256>>>(pairs, n_edges);
    node_kernel<<<296, 256, NODE_SMEM>>>(X, W1, b1, W2, b2, We1, be1, n_nodes);
    edge_kernel<<<444, 128, EDGE_SMEM>>>(We1, We2, be2, out, n_edges);
}

// round 12
// speedup vs baseline: 5.4470x; 1.0611x over previous
#include <cuda_runtime.h>
#include <cuda_fp16.h>

#define HID 64
#define MAX_NODES 100000
#define ST 36              // sD/sPQ row stride in uints
#define NODE_SMEM ((3 * 4096 + 128 * 68) * 4)
#define EDGE_SMEM ((64 + 4 * 2 * 32 * ST) * 4)

typedef unsigned int uint;
typedef unsigned long long ull;

__device__ __half g_Hh[MAX_NODES * HID];
__device__ __half g_Ph[MAX_NODES * HID];
__device__ __half g_Qh[MAX_NODES * HID];
__device__ int    g_is64;

__device__ __forceinline__ void mma_f16(float4& d, const uint* a, uint b0, uint b1) {
    asm volatile(
        "mma.sync.aligned.m16n8k16.row.col.f32.f16.f16.f32 "
        "{%0,%1,%2,%3}, {%4,%5,%6,%7}, {%8,%9}, {%0,%1,%2,%3};"
        : "+f"(d.x), "+f"(d.y), "+f"(d.z), "+f"(d.w)
        : "r"(a[0]), "r"(a[1]), "r"(a[2]), "r"(a[3]), "r"(b0), "r"(b1));
}
__device__ __forceinline__ ull pack2(float x, float y) {
    ull r; asm("mov.b64 %0, {%1, %2};" : "=l"(r) : "f"(x), "f"(y)); return r;
}
__device__ __forceinline__ void unpack2(ull v, float& x, float& y) {
    asm("mov.b64 {%0, %1}, %2;" : "=f"(x), "=f"(y) : "l"(v));
}
__device__ __forceinline__ ull ffma2(ull a, ull b, ull c) {
    ull r; asm("fma.rn.f32x2 %0, %1, %2, %3;" : "=l"(r) : "l"(a), "l"(b), "l"(c));
    return r;
}

// ---------------------------------------------------------------------------
// detect int64 vs int32 pairs (reads only first 2*n_edges words, in-bounds
// for both dtypes; int64 -> odd words all zero).
// ---------------------------------------------------------------------------
__global__ void detect_kernel(const int* __restrict__ w, int n_edges) {
    __shared__ int any_nz;
    if (threadIdx.x == 0) any_nz = 0;
    __syncthreads();
    int nz = 0;
    for (int j = threadIdx.x; j < 4096; j += blockDim.x) {
        long long idx = 1 + 2 * ((long long)j * (n_edges - 1) / 4096);
        if (idx < 2LL * n_edges) nz |= w[idx];
    }
    if (nz) atomicOr(&any_nz, 1);
    __syncthreads();
    if (threadIdx.x == 0) g_is64 = (any_nz == 0) ? 1 : 0;
}

// ---------------------------------------------------------------------------
// Node kernel: 128-node tiles, 8 nodes x 4 dims per thread, k-step-2.
// ---------------------------------------------------------------------------
__global__ __launch_bounds__(256, 2) void node_kernel(
        const float* __restrict__ X,
        const float* __restrict__ W1, const float* __restrict__ b1,
        const float* __restrict__ W2, const float* __restrict__ b2,
        const float* __restrict__ We1, const float* __restrict__ be1,
        int n_nodes) {
    extern __shared__ float ns[];
    float* sW2 = ns;
    float* sA  = ns + 4096;
    float* sB  = ns + 8192;
    float* sh  = ns + 12288;        // [128][68]

    int tid = threadIdx.x;
    for (int i = tid; i < 4096; i += 256) {
        sW2[i] = W2[i];
        sA[i]  = We1[i];
        sB[i]  = We1[4096 + i];
    }

    int q = tid & 15;
    int g = tid >> 4;

    float w1r[4][4];
    #pragma unroll
    for (int c = 0; c < 4; c++) {
        float4 w = *(const float4*)&W1[c * HID + 4 * q];
        w1r[c][0] = w.x; w1r[c][1] = w.y; w1r[c][2] = w.z; w1r[c][3] = w.w;
    }
    float4 b1r  = *(const float4*)&b1[4 * q];
    float4 b2r  = *(const float4*)&b2[4 * q];
    float4 be1r = *(const float4*)&be1[4 * q];
    __syncthreads();

    for (int base = blockIdx.x * 128; base < n_nodes; base += gridDim.x * 128) {
        #pragma unroll
        for (int i = 0; i < 8; i++) {
            int node = base + 8 * g + i;
            float4 x = (node < n_nodes) ? *(const float4*)&X[(size_t)node * 4]
                                        : make_float4(0.f, 0.f, 0.f, 0.f);
            #pragma unroll
            for (int m = 0; m < 4; m++) {
                float h = ((const float*)&b1r)[m];
                h = fmaf(x.x, w1r[0][m], h);
                h = fmaf(x.y, w1r[1][m], h);
                h = fmaf(x.z, w1r[2][m], h);
                h = fmaf(x.w, w1r[3][m], h);
                sh[(8 * g + i) * 68 + 4 * q + m] = fmaxf(h, 0.f);
            }
        }
        __syncthreads();

        ull a0[8], a1[8];
        #pragma unroll
        for (int i = 0; i < 8; i++) {
            a0[i] = pack2(b2r.x, b2r.y);
            a1[i] = pack2(b2r.z, b2r.w);
        }
        #pragma unroll 4
        for (int k = 0; k < HID; k += 2) {
            ulonglong2 w0 = *(const ulonglong2*)&sW2[k * HID + 4 * q];
            ulonglong2 w1 = *(const ulonglong2*)&sW2[(k + 1) * HID + 4 * q];
            #pragma unroll
            for (int i = 0; i < 8; i++) {
                float2 h2 = *(const float2*)&sh[(8 * g + i) * 68 + k];
                ull hs0 = pack2(h2.x, h2.x);
                ull hs1 = pack2(h2.y, h2.y);
                a0[i] = ffma2(hs0, w0.x, a0[i]);
                a1[i] = ffma2(hs0, w0.y, a1[i]);
                a0[i] = ffma2(hs1, w1.x, a0[i]);
                a1[i] = ffma2(hs1, w1.y, a1[i]);
            }
        }
        float hv[8][4];
        #pragma unroll
        for (int i = 0; i < 8; i++) {
            unpack2(a0[i], hv[i][0], hv[i][1]);
            unpack2(a1[i], hv[i][2], hv[i][3]);
            #pragma unroll
            for (int m = 0; m < 4; m++) hv[i][m] = fmaxf(hv[i][m], 0.f);
        }
        __syncthreads();

        #pragma unroll
        for (int i = 0; i < 8; i++) {
            #pragma unroll
            for (int m = 0; m < 4; m++)
                sh[(8 * g + i) * 68 + 4 * q + m] = hv[i][m];
            int node = base + 8 * g + i;
            if (node < n_nodes) {
                __half2 h01 = __floats2half2_rn(hv[i][0], hv[i][1]);
                __half2 h23 = __floats2half2_rn(hv[i][2], hv[i][3]);
                *(uint2*)&g_Hh[(size_t)node * HID + 4 * q] =
                    make_uint2(*(uint*)&h01, *(uint*)&h23);
            }
        }
        __syncthreads();

        ull p0[8], p1[8], q0[8], q1[8];
        #pragma unroll
        for (int i = 0; i < 8; i++) {
            p0[i] = pack2(be1r.x, be1r.y);
            p1[i] = pack2(be1r.z, be1r.w);
            q0[i] = pack2(0.f, 0.f);
            q1[i] = pack2(0.f, 0.f);
        }
        #pragma unroll 2
        for (int k = 0; k < HID; k += 2) {
            ulonglong2 av0 = *(const ulonglong2*)&sA[k * HID + 4 * q];
            ulonglong2 av1 = *(const ulonglong2*)&sA[(k + 1) * HID + 4 * q];
            ulonglong2 bv0 = *(const ulonglong2*)&sB[k * HID + 4 * q];
            ulonglong2 bv1 = *(const ulonglong2*)&sB[(k + 1) * HID + 4 * q];
            #pragma unroll
            for (int i = 0; i < 8; i++) {
                float2 h2 = *(const float2*)&sh[(8 * g + i) * 68 + k];
                ull hs0 = pack2(h2.x, h2.x);
                ull hs1 = pack2(h2.y, h2.y);
                p0[i] = ffma2(hs0, av0.x, p0[i]);
                p1[i] = ffma2(hs0, av0.y, p1[i]);
                q0[i] = ffma2(hs0, bv0.x, q0[i]);
                q1[i] = ffma2(hs0, bv0.y, q1[i]);
                p0[i] = ffma2(hs1, av1.x, p0[i]);
                p1[i] = ffma2(hs1, av1.y, p1[i]);
                q0[i] = ffma2(hs1, bv1.x, q0[i]);
                q1[i] = ffma2(hs1, bv1.y, q1[i]);
            }
        }
        #pragma unroll
        for (int i = 0; i < 8; i++) {
            int node = base + 8 * g + i;
            if (node < n_nodes) {
                float x0, x1, x2, x3;
                unpack2(p0[i], x0, x1); unpack2(p1[i], x2, x3);
                __half2 h01 = __floats2half2_rn(x0, x1);
                __half2 h23 = __floats2half2_rn(x2, x3);
                *(uint2*)&g_Ph[(size_t)node * HID + 4 * q] =
                    make_uint2(*(uint*)&h01, *(uint*)&h23);
                unpack2(q0[i], x0, x1); unpack2(q1[i], x2, x3);
                h01 = __floats2half2_rn(x0, x1);
                h23 = __floats2half2_rn(x2, x3);
                *(uint2*)&g_Qh[(size_t)node * HID + 4 * q] =
                    make_uint2(*(uint*)&h01, *(uint*)&h23);
            }
        }
        __syncthreads();
    }
}

// ---------------------------------------------------------------------------
// Edge kernel v12: reads pairs directly (uniform g_is64 branch; decode kernel
// eliminated). m-split mainloop halves live accumulators -> 4 blocks/SM.
// ---------------------------------------------------------------------------
__global__ __launch_bounds__(128, 4) void edge_kernel(
        const int* __restrict__ pairs,
        const float* __restrict__ We1,
        const float* __restrict__ We2,
        const float* __restrict__ be2,
        float* __restrict__ out,
        int n_edges) {
    extern __shared__ uint es12[];
    float* sW2 = (float*)es12;               // [64]
    uint*  sDall = es12 + 64;                // 4 warps x (sD[32][ST], sPQ[32][ST])

    int tid  = threadIdx.x;
    int lane = tid & 31;
    int wid  = tid >> 5;
    uint* sD  = sDall + wid * 2 * 32 * ST;
    uint* sPQ = sD + 32 * ST;

    int c = lane & 3;
    int r = lane >> 2;

    // B(C) fragments in registers, loaded once.
    const float* C = We1 + 2 * HID * HID;
    uint breg[4][8][2];
    #pragma unroll
    for (int kt = 0; kt < 4; kt++)
        #pragma unroll
        for (int nt = 0; nt < 8; nt++) {
            int n  = 8 * nt + r;
            int k0 = 16 * kt + 2 * c;
            int k1 = 16 * kt + 8 + 2 * c;
            __half2 h0 = __floats2half2_rn(C[k0 * HID + n], C[(k0 + 1) * HID + n]);
            __half2 h1 = __floats2half2_rn(C[k1 * HID + n], C[(k1 + 1) * HID + n]);
            breg[kt][nt][0] = *(uint*)&h0;
            breg[kt][nt][1] = *(uint*)&h1;
        }
    if (tid < HID) sW2[tid] = We2[tid];
    __syncthreads();

    int txg = lane & 7;
    int tyg = lane >> 3;
    float bias = be2[0];
    int is64 = g_is64;

    int n_wt = (n_edges + 31) >> 5;

    for (int t0 = blockIdx.x * 4 + wid; t0 < n_wt; t0 += gridDim.x * 4) {
        int ebase = t0 * 32;

        // ---- gather H diffs -> sD, P+Q -> sPQ (fp16, coalesced) ----
        #pragma unroll
        for (int i = 0; i < 8; i++) {
            int e  = 8 * tyg + i;
            int eg = ebase + e;
            int u = 0, v = 0;
            if (eg < n_edges) {
                if (is64) { u = pairs[4LL * eg]; v = pairs[4LL * eg + 2]; }
                else      { u = pairs[2LL * eg]; v = pairs[2LL * eg + 1]; }
            }
            uint4 hu = *(const uint4*)&g_Hh[(size_t)u * HID + 8 * txg];
            uint4 hv = *(const uint4*)&g_Hh[(size_t)v * HID + 8 * txg];
            uint4 pu = *(const uint4*)&g_Ph[(size_t)u * HID + 8 * txg];
            uint4 qv = *(const uint4*)&g_Qh[(size_t)v * HID + 8 * txg];
            uint4 d, s;
            __half2 t;
            t = __habs2(__hsub2(*(__half2*)&hu.x, *(__half2*)&hv.x)); d.x = *(uint*)&t;
            t = __habs2(__hsub2(*(__half2*)&hu.y, *(__half2*)&hv.y)); d.y = *(uint*)&t;
            t = __habs2(__hsub2(*(__half2*)&hu.z, *(__half2*)&hv.z)); d.z = *(uint*)&t;
            t = __habs2(__hsub2(*(__half2*)&hu.w, *(__half2*)&hv.w)); d.w = *(uint*)&t;
            t = __hadd2(*(__half2*)&pu.x, *(__half2*)&qv.x); s.x = *(uint*)&t;
            t = __hadd2(*(__half2*)&pu.y, *(__half2*)&qv.y); s.y = *(uint*)&t;
            t = __hadd2(*(__half2*)&pu.z, *(__half2*)&qv.z); s.z = *(uint*)&t;
            t = __hadd2(*(__half2*)&pu.w, *(__half2*)&qv.w); s.w = *(uint*)&t;
            *(uint4*)&sD[e * ST + 4 * txg]  = d;
            *(uint4*)&sPQ[e * ST + 4 * txg] = s;
        }
        __syncwarp();

        // ---- m-split: mma + epilogue per 16-edge half ----
        #pragma unroll
        for (int m = 0; m < 2; m++) {
            float4 acc[8];
            #pragma unroll
            for (int nt = 0; nt < 8; nt++)
                acc[nt] = make_float4(0.f, 0.f, 0.f, 0.f);

            #pragma unroll
            for (int kt = 0; kt < 4; kt++) {
                uint a[4];
                a[0] = sD[(16 * m + r)     * ST + 8 * kt + c];
                a[1] = sD[(16 * m + 8 + r) * ST + 8 * kt + c];
                a[2] = sD[(16 * m + r)     * ST + 8 * kt + 4 + c];
                a[3] = sD[(16 * m + 8 + r) * ST + 8 * kt + 4 + c];
                #pragma unroll
                for (int nt = 0; nt < 8; nt++)
                    mma_f16(acc[nt], a, breg[kt][nt][0], breg[kt][nt][1]);
            }

            float sLo = 0.f, sHi = 0.f;
            #pragma unroll
            for (int nt = 0; nt < 8; nt++) {
                float w0 = sW2[8 * nt + 2 * c];
                float w1 = sW2[8 * nt + 2 * c + 1];
                uint pqL = sPQ[(16 * m + r)     * ST + 4 * nt + c];
                uint pqH = sPQ[(16 * m + 8 + r) * ST + 4 * nt + c];
                float2 lo = __half22float2(*(__half2*)&pqL);
                float2 hi = __half22float2(*(__half2*)&pqH);
                sLo = fmaf(fmaxf(acc[nt].x + lo.x, 0.f), w0, sLo);
                sLo = fmaf(fmaxf(acc[nt].y + lo.y, 0.f), w1, sLo);
                sHi = fmaf(fmaxf(acc[nt].z + hi.x, 0.f), w0, sHi);
                sHi = fmaf(fmaxf(acc[nt].w + hi.y, 0.f), w1, sHi);
            }
            sLo += __shfl_xor_sync(0xffffffffu, sLo, 1);
            sLo += __shfl_xor_sync(0xffffffffu, sLo, 2);
            sHi += __shfl_xor_sync(0xffffffffu, sHi, 1);
            sHi += __shfl_xor_sync(0xffffffffu, sHi, 2);
            if (c == 0) {
                int eLo = ebase + 16 * m + r;
                int eHi = eLo + 8;
                if (eLo < n_edges) out[eLo] = sLo + bias;
                if (eHi < n_edges) out[eHi] = sHi + bias;
            }
        }
        __syncwarp();   // all reads done before next tile overwrites sD/sPQ
    }
}

// ---------------------------------------------------------------------------
extern "C" void kernel_launch(void* const* d_in, const int* in_sizes, int n_in,
                              void* d_out, int out_size) {
    const float* X     = (const float*)d_in[0];
    const int*   pairs = (const int*)d_in[1];
    const float* W1    = (const float*)d_in[2];
    const float* b1    = (const float*)d_in[3];
    const float* W2    = (const float*)d_in[4];
    const float* b2    = (const float*)d_in[5];
    const float* We1   = (const float*)d_in[6];
    const float* be1   = (const float*)d_in[7];
    const float* We2   = (const float*)d_in[8];
    const float* be2   = (const float*)d_in[9];
    float* out = (float*)d_out;

    int n_nodes = in_sizes[0] / 4;
    int n_edges = out_size;

    cudaFuncSetAttribute(node_kernel,
                         cudaFuncAttributeMaxDynamicSharedMemorySize, NODE_SMEM);
    cudaFuncSetAttribute(edge_kernel,
                         cudaFuncAttributeMaxDynamicSharedMemorySize, EDGE_SMEM);

    detect_kernel<<<1, 256>>>(pairs, n_edges);
    node_kernel<<<296, 256, NODE_SMEM>>>(X, W1, b1, W2, b2, We1, be1, n_nodes);
    edge_kernel<<<592, 128, EDGE_SMEM>>>(pairs, We1, We2, be2, out, n_edges);
}

// round 13
// speedup vs baseline: 7.5952x; 1.3944x over previous
#include <cuda_runtime.h>
#include <cuda_fp16.h>

#define HID 64
#define MAX_NODES 100000
#define ST 36              // sD/sPQ/sh row stride in uints (ldmatrix conflict-free)
// node smem: 3 frag arrays (3*2048 uints) + sh (128*36) + bias (128 f)
#define NODE_SMEM ((3 * 2048 + 128 * 36 + 128) * 4)
#define EDGE_SMEM ((64 + 4 * 2 * 32 * ST) * 4)

typedef unsigned int uint;

__device__ __half g_Hh[MAX_NODES * HID];
__device__ __half g_Ph[MAX_NODES * HID];
__device__ __half g_Qh[MAX_NODES * HID];
__device__ int    g_is64;

__device__ __forceinline__ void mma_f16(float4& d, const uint* a, uint b0, uint b1) {
    asm volatile(
        "mma.sync.aligned.m16n8k16.row.col.f32.f16.f16.f32 "
        "{%0,%1,%2,%3}, {%4,%5,%6,%7}, {%8,%9}, {%0,%1,%2,%3};"
        : "+f"(d.x), "+f"(d.y), "+f"(d.z), "+f"(d.w)
        : "r"(a[0]), "r"(a[1]), "r"(a[2]), "r"(a[3]), "r"(b0), "r"(b1));
}
__device__ __forceinline__ void ldm_x4(uint a[4], uint saddr) {
    asm volatile(
        "ldmatrix.sync.aligned.m8n8.x4.shared.b16 {%0,%1,%2,%3}, [%4];"
        : "=r"(a[0]), "=r"(a[1]), "=r"(a[2]), "=r"(a[3]) : "r"(saddr));
}
__device__ __forceinline__ uint smem_u32(const void* p) {
    return (uint)__cvta_generic_to_shared(p);
}

// ---------------------------------------------------------------------------
// Node kernel v13: per 128-node tile, per-warp-private 16-row slices.
//  phase1 (fp32 scalar): h1 = relu(X@W1+b1) -> sh (fp16)
//  phase2 (fp16 MMA):    H  = relu(h1@W2+b2) -> sh (overwrite) + g_Hh
//  phase3 (fp16 MMA):    P  = H@A+be1 -> g_Ph ; Q = H@B -> g_Qh
// Block 0 additionally detects int64-vs-int32 pairs (odd words all zero
// over 256 samples => int64); only the first 2*n_edges int32 words are read.
// ---------------------------------------------------------------------------
__global__ __launch_bounds__(256, 2) void node_kernel(
        const float* __restrict__ X,
        const float* __restrict__ W1, const float* __restrict__ b1,
        const float* __restrict__ W2, const float* __restrict__ b2,
        const float* __restrict__ We1, const float* __restrict__ be1,
        int n_nodes,
        const int* __restrict__ pairs_w, int n_edges) {
    extern __shared__ uint nsm[];
    uint*  sFr   = nsm;                     // [3][2048] frag-major W2, A, B
    uint*  sh    = nsm + 3 * 2048;          // [128][36] fp16 tile (h1 then H)
    float* sbias = (float*)(nsm + 3 * 2048 + 128 * 36);  // b2[64], be1[64]

    int tid = threadIdx.x;

    // ---- dtype detection (block 0 only) ----
    if (blockIdx.x == 0) {
        int nz = 0;
        long long idx = 1 + 2 * ((long long)tid * (n_edges - 1) / 256);
        if (idx < 2LL * n_edges) nz = pairs_w[idx];
        int any = __syncthreads_or(nz);
        if (tid == 0) g_is64 = (any == 0) ? 1 : 0;
    }

    // ---- build fp16 fragment-major weights ----
    for (int idx = tid; idx < 3 * 2048; idx += 256) {
        int arr = idx >> 11;
        int id  = idx & 2047;
        int which = id & 1;
        int ln    = (id >> 1) & 31;
        int nt    = (id >> 6) & 7;
        int kt    = id >> 9;
        int cc = ln & 3;
        int rr = ln >> 2;
        int k0 = 16 * kt + (which ? 8 : 0) + 2 * cc;
        int n  = 8 * nt + rr;
        const float* W = (arr == 0) ? W2 : (We1 + (size_t)(arr - 1) * 4096);
        __half2 h = __floats2half2_rn(W[k0 * HID + n], W[(k0 + 1) * HID + n]);
        sFr[idx] = *(uint*)&h;
    }
    if (tid < 64)  sbias[tid] = b2[tid];
    else if (tid < 128) sbias[tid] = be1[tid - 64];

    int q = tid & 15;
    int g = tid >> 4;
    int lane = tid & 31;
    int w    = tid >> 5;
    int c = lane & 3;
    int r = lane >> 2;

    float w1r[4][4];
    #pragma unroll
    for (int cc = 0; cc < 4; cc++) {
        float4 wv = *(const float4*)&W1[cc * HID + 4 * q];
        w1r[cc][0] = wv.x; w1r[cc][1] = wv.y; w1r[cc][2] = wv.z; w1r[cc][3] = wv.w;
    }
    float4 b1r = *(const float4*)&b1[4 * q];

    uint* sW2f = sFr;
    uint* sAf  = sFr + 2048;
    uint* sBf  = sFr + 4096;
    uint shbase = smem_u32(sh);
    uint aaddr0 = shbase + (((16 * w + (lane & 15)) * ST + 4 * (lane >> 4)) << 2);
    __syncthreads();

    for (int tb = blockIdx.x * 128; tb < n_nodes; tb += gridDim.x * 128) {
        // ---- phase 1: h1 = relu(X@W1+b1) -> sh fp16 ----
        #pragma unroll
        for (int i = 0; i < 8; i++) {
            int node = tb + 8 * g + i;
            float4 x = (node < n_nodes) ? *(const float4*)&X[(size_t)node * 4]
                                        : make_float4(0.f, 0.f, 0.f, 0.f);
            float h[4];
            #pragma unroll
            for (int m = 0; m < 4; m++) {
                float hh = ((const float*)&b1r)[m];
                hh = fmaf(x.x, w1r[0][m], hh);
                hh = fmaf(x.y, w1r[1][m], hh);
                hh = fmaf(x.z, w1r[2][m], hh);
                hh = fmaf(x.w, w1r[3][m], hh);
                h[m] = fmaxf(hh, 0.f);
            }
            __half2 h01 = __floats2half2_rn(h[0], h[1]);
            __half2 h23 = __floats2half2_rn(h[2], h[3]);
            *(uint2*)&sh[(8 * g + i) * ST + 2 * q] =
                make_uint2(*(uint*)&h01, *(uint*)&h23);
        }
        __syncwarp();

        // ---- phase 2: H = relu(h1@W2+b2), write fp16 back into sh ----
        {
            float4 acc[8];
            #pragma unroll
            for (int nt = 0; nt < 8; nt++) acc[nt] = make_float4(0.f, 0.f, 0.f, 0.f);
            #pragma unroll
            for (int kt = 0; kt < 4; kt++) {
                uint a[4];
                ldm_x4(a, aaddr0 + kt * 32);
                #pragma unroll
                for (int nt = 0; nt < 8; nt++) {
                    uint2 b = *(const uint2*)&sW2f[((kt * 8 + nt) * 32 + lane) * 2];
                    mma_f16(acc[nt], a, b.x, b.y);
                }
            }
            __syncwarp();      // all h1 reads done before overwrite
            #pragma unroll
            for (int nt = 0; nt < 8; nt++) {
                float2 bv = *(const float2*)&sbias[8 * nt + 2 * c];
                __half2 lo = __floats2half2_rn(fmaxf(acc[nt].x + bv.x, 0.f),
                                               fmaxf(acc[nt].y + bv.y, 0.f));
                __half2 hi = __floats2half2_rn(fmaxf(acc[nt].z + bv.x, 0.f),
                                               fmaxf(acc[nt].w + bv.y, 0.f));
                sh[(16 * w + r) * ST + 4 * nt + c]     = *(uint*)&lo;
                sh[(16 * w + 8 + r) * ST + 4 * nt + c] = *(uint*)&hi;
            }
        }
        __syncwarp();

        // ---- phase 3: P = H@A+be1, Q = H@B ----
        {
            float4 pA[8], qA[8];
            #pragma unroll
            for (int nt = 0; nt < 8; nt++) {
                pA[nt] = make_float4(0.f, 0.f, 0.f, 0.f);
                qA[nt] = make_float4(0.f, 0.f, 0.f, 0.f);
            }
            #pragma unroll
            for (int kt = 0; kt < 4; kt++) {
                uint a[4];
                ldm_x4(a, aaddr0 + kt * 32);
                #pragma unroll
                for (int nt = 0; nt < 8; nt++) {
                    uint2 ba = *(const uint2*)&sAf[((kt * 8 + nt) * 32 + lane) * 2];
                    uint2 bb = *(const uint2*)&sBf[((kt * 8 + nt) * 32 + lane) * 2];
                    mma_f16(pA[nt], a, ba.x, ba.y);
                    mma_f16(qA[nt], a, bb.x, bb.y);
                }
            }
            int nodeLo = tb + 16 * w + r;
            int nodeHi = nodeLo + 8;
            #pragma unroll
            for (int nt = 0; nt < 8; nt++) {
                float2 be = *(const float2*)&sbias[64 + 8 * nt + 2 * c];
                if (nodeLo < n_nodes) {
                    __half2 p = __floats2half2_rn(pA[nt].x + be.x, pA[nt].y + be.y);
                    __half2 qq = __floats2half2_rn(qA[nt].x, qA[nt].y);
                    *(uint*)&g_Ph[(size_t)nodeLo * HID + 8 * nt + 2 * c] = *(uint*)&p;
                    *(uint*)&g_Qh[(size_t)nodeLo * HID + 8 * nt + 2 * c] = *(uint*)&qq;
                }
                if (nodeHi < n_nodes) {
                    __half2 p = __floats2half2_rn(pA[nt].z + be.x, pA[nt].w + be.y);
                    __half2 qq = __floats2half2_rn(qA[nt].z, qA[nt].w);
                    *(uint*)&g_Ph[(size_t)nodeHi * HID + 8 * nt + 2 * c] = *(uint*)&p;
                    *(uint*)&g_Qh[(size_t)nodeHi * HID + 8 * nt + 2 * c] = *(uint*)&qq;
                }
            }
        }

        // ---- H -> gmem (coalesced from sh) ----
        #pragma unroll
        for (int it = 0; it < 4; it++) {
            int id2 = it * 32 + lane;
            int row = id2 >> 3, ch = id2 & 7;
            int node = tb + 16 * w + row;
            if (node < n_nodes)
                *(uint4*)&g_Hh[(size_t)node * HID + ch * 8] =
                    *(const uint4*)&sh[(16 * w + row) * ST + ch * 4];
        }
        __syncwarp();      // sh reads done before next tile's phase 1
    }
}

// ---------------------------------------------------------------------------
// Edge kernel v13: direct pairs read, register B-frags, ldmatrix A-frags,
// m-split mainloop. Warp tile = 32 edges; warp-autonomous.
// ---------------------------------------------------------------------------
__global__ __launch_bounds__(128, 4) void edge_kernel(
        const int* __restrict__ pairs,
        const float* __restrict__ We1,
        const float* __restrict__ We2,
        const float* __restrict__ be2,
        float* __restrict__ out,
        int n_edges) {
    extern __shared__ uint es13[];
    float* sW2 = (float*)es13;               // [64]
    uint*  sDall = es13 + 64;                // 4 warps x (sD[32][ST], sPQ[32][ST])

    int tid  = threadIdx.x;
    int lane = tid & 31;
    int wid  = tid >> 5;
    uint* sD  = sDall + wid * 2 * 32 * ST;
    uint* sPQ = sD + 32 * ST;

    int c = lane & 3;
    int r = lane >> 2;

    // B(C) fragments in registers, loaded once.
    const float* C = We1 + 2 * HID * HID;
    uint breg[4][8][2];
    #pragma unroll
    for (int kt = 0; kt < 4; kt++)
        #pragma unroll
        for (int nt = 0; nt < 8; nt++) {
            int n  = 8 * nt + r;
            int k0 = 16 * kt + 2 * c;
            int k1 = 16 * kt + 8 + 2 * c;
            __half2 h0 = __floats2half2_rn(C[k0 * HID + n], C[(k0 + 1) * HID + n]);
            __half2 h1 = __floats2half2_rn(C[k1 * HID + n], C[(k1 + 1) * HID + n]);
            breg[kt][nt][0] = *(uint*)&h0;
            breg[kt][nt][1] = *(uint*)&h1;
        }
    if (tid < HID) sW2[tid] = We2[tid];
    __syncthreads();

    int txg = lane & 7;
    int tyg = lane >> 3;
    float bias = be2[0];
    int is64 = g_is64;
    uint sdbase = smem_u32(sD);

    int n_wt = (n_edges + 31) >> 5;

    for (int t0 = blockIdx.x * 4 + wid; t0 < n_wt; t0 += gridDim.x * 4) {
        int ebase = t0 * 32;

        // ---- gather H diffs -> sD, P+Q -> sPQ (fp16, coalesced) ----
        #pragma unroll
        for (int i = 0; i < 8; i++) {
            int e  = 8 * tyg + i;
            int eg = ebase + e;
            int u = 0, v = 0;
            if (eg < n_edges) {
                if (is64) { u = pairs[4LL * eg]; v = pairs[4LL * eg + 2]; }
                else      { u = pairs[2LL * eg]; v = pairs[2LL * eg + 1]; }
            }
            uint4 hu = *(const uint4*)&g_Hh[(size_t)u * HID + 8 * txg];
            uint4 hv = *(const uint4*)&g_Hh[(size_t)v * HID + 8 * txg];
            uint4 pu = *(const uint4*)&g_Ph[(size_t)u * HID + 8 * txg];
            uint4 qv = *(const uint4*)&g_Qh[(size_t)v * HID + 8 * txg];
            uint4 d, s;
            __half2 t;
            t = __habs2(__hsub2(*(__half2*)&hu.x, *(__half2*)&hv.x)); d.x = *(uint*)&t;
            t = __habs2(__hsub2(*(__half2*)&hu.y, *(__half2*)&hv.y)); d.y = *(uint*)&t;
            t = __habs2(__hsub2(*(__half2*)&hu.z, *(__half2*)&hv.z)); d.z = *(uint*)&t;
            t = __habs2(__hsub2(*(__half2*)&hu.w, *(__half2*)&hv.w)); d.w = *(uint*)&t;
            t = __hadd2(*(__half2*)&pu.x, *(__half2*)&qv.x); s.x = *(uint*)&t;
            t = __hadd2(*(__half2*)&pu.y, *(__half2*)&qv.y); s.y = *(uint*)&t;
            t = __hadd2(*(__half2*)&pu.z, *(__half2*)&qv.z); s.z = *(uint*)&t;
            t = __hadd2(*(__half2*)&pu.w, *(__half2*)&qv.w); s.w = *(uint*)&t;
            *(uint4*)&sD[e * ST + 4 * txg]  = d;
            *(uint4*)&sPQ[e * ST + 4 * txg] = s;
        }
        __syncwarp();

        // ---- m-split: mma + epilogue per 16-edge half ----
        #pragma unroll
        for (int m = 0; m < 2; m++) {
            uint aaddr = sdbase + (((16 * m + (lane & 15)) * ST + 4 * (lane >> 4)) << 2);
            float4 acc[8];
            #pragma unroll
            for (int nt = 0; nt < 8; nt++)
                acc[nt] = make_float4(0.f, 0.f, 0.f, 0.f);

            #pragma unroll
            for (int kt = 0; kt < 4; kt++) {
                uint a[4];
                ldm_x4(a, aaddr + kt * 32);
                #pragma unroll
                for (int nt = 0; nt < 8; nt++)
                    mma_f16(acc[nt], a, breg[kt][nt][0], breg[kt][nt][1]);
            }

            float sLo = 0.f, sHi = 0.f;
            #pragma unroll
            for (int nt = 0; nt < 8; nt++) {
                float w0 = sW2[8 * nt + 2 * c];
                float w1 = sW2[8 * nt + 2 * c + 1];
                uint pqL = sPQ[(16 * m + r)     * ST + 4 * nt + c];
                uint pqH = sPQ[(16 * m + 8 + r) * ST + 4 * nt + c];
                float2 lo = __half22float2(*(__half2*)&pqL);
                float2 hi = __half22float2(*(__half2*)&pqH);
                sLo = fmaf(fmaxf(acc[nt].x + lo.x, 0.f), w0, sLo);
                sLo = fmaf(fmaxf(acc[nt].y + lo.y, 0.f), w1, sLo);
                sHi = fmaf(fmaxf(acc[nt].z + hi.x, 0.f), w0, sHi);
                sHi = fmaf(fmaxf(acc[nt].w + hi.y, 0.f), w1, sHi);
            }
            sLo += __shfl_xor_sync(0xffffffffu, sLo, 1);
            sLo += __shfl_xor_sync(0xffffffffu, sLo, 2);
            sHi += __shfl_xor_sync(0xffffffffu, sHi, 1);
            sHi += __shfl_xor_sync(0xffffffffu, sHi, 2);
            if (c == 0) {
                int eLo = ebase + 16 * m + r;
                int eHi = eLo + 8;
                if (eLo < n_edges) out[eLo] = sLo + bias;
                if (eHi < n_edges) out[eHi] = sHi + bias;
            }
        }
        __syncwarp();   // all reads done before next tile overwrites sD/sPQ
    }
}

// ---------------------------------------------------------------------------
extern "C" void kernel_launch(void* const* d_in, const int* in_sizes, int n_in,
                              void* d_out, int out_size) {
    const float* X     = (const float*)d_in[0];
    const int*   pairs = (const int*)d_in[1];
    const float* W1    = (const float*)d_in[2];
    const float* b1    = (const float*)d_in[3];
    const float* W2    = (const float*)d_in[4];
    const float* b2    = (const float*)d_in[5];
    const float* We1   = (const float*)d_in[6];
    const float* be1   = (const float*)d_in[7];
    const float* We2   = (const float*)d_in[8];
    const float* be2   = (const float*)d_in[9];
    float* out = (float*)d_out;

    int n_nodes = in_sizes[0] / 4;
    int n_edges = out_size;

    cudaFuncSetAttribute(node_kernel,
                         cudaFuncAttributeMaxDynamicSharedMemorySize, NODE_SMEM);
    cudaFuncSetAttribute(edge_kernel,
                         cudaFuncAttributeMaxDynamicSharedMemorySize, EDGE_SMEM);

    node_kernel<<<296, 256, NODE_SMEM>>>(X, W1, b1, W2, b2, We1, be1,
                                         n_nodes, pairs, n_edges);
    edge_kernel<<<592, 128, EDGE_SMEM>>>(pairs, We1, We2, be2, out, n_edges);
}

// round 14
// speedup vs baseline: 7.7742x; 1.0236x over previous
#include <cuda_runtime.h>
#include <cuda_fp16.h>

#define HID 64
#define MAX_NODES 100000
#define ST 36              // sD/sPQ/sh row stride in uints (ldmatrix conflict-free)
#define NODE_SMEM ((3 * 2048 + 128 * 36 + 128) * 4)
#define EDGE_SMEM ((64 + 4 * 2 * 32 * ST) * 4)

typedef unsigned int uint;

__device__ __half g_Hh[MAX_NODES * HID];
__device__ __half g_Ph[MAX_NODES * HID];
__device__ __half g_Qh[MAX_NODES * HID];
__device__ int    g_is64;

__device__ __forceinline__ void mma_f16(float4& d, const uint* a, uint b0, uint b1) {
    asm volatile(
        "mma.sync.aligned.m16n8k16.row.col.f32.f16.f16.f32 "
        "{%0,%1,%2,%3}, {%4,%5,%6,%7}, {%8,%9}, {%0,%1,%2,%3};"
        : "+f"(d.x), "+f"(d.y), "+f"(d.z), "+f"(d.w)
        : "r"(a[0]), "r"(a[1]), "r"(a[2]), "r"(a[3]), "r"(b0), "r"(b1));
}
__device__ __forceinline__ void ldm_x4(uint a[4], uint saddr) {
    asm volatile(
        "ldmatrix.sync.aligned.m8n8.x4.shared.b16 {%0,%1,%2,%3}, [%4];"
        : "=r"(a[0]), "=r"(a[1]), "=r"(a[2]), "=r"(a[3]) : "r"(saddr));
}
__device__ __forceinline__ uint smem_u32(const void* p) {
    return (uint)__cvta_generic_to_shared(p);
}

// ---------------------------------------------------------------------------
// Node kernel: per 128-node tile, per-warp-private 16-row slices.
//  phase1 (fp32): h1 = relu(X@W1+b1) -> sh fp16
//  phase2 (MMA):  H  = relu(h1@W2+b2) -> sh + g_Hh
//  phase3 (MMA):  P  = H@A+be1 -> g_Ph ; Q = H@B -> g_Qh
// Block 0 detects int64-vs-int32 pairs.
// ---------------------------------------------------------------------------
__global__ __launch_bounds__(256, 2) void node_kernel(
        const float* __restrict__ X,
        const float* __restrict__ W1, const float* __restrict__ b1,
        const float* __restrict__ W2, const float* __restrict__ b2,
        const float* __restrict__ We1, const float* __restrict__ be1,
        int n_nodes,
        const int* __restrict__ pairs_w, int n_edges) {
    extern __shared__ uint nsm[];
    uint*  sFr   = nsm;                     // [3][2048] frag-major W2, A, B
    uint*  sh    = nsm + 3 * 2048;          // [128][36] fp16 tile
    float* sbias = (float*)(nsm + 3 * 2048 + 128 * 36);

    int tid = threadIdx.x;

    if (blockIdx.x == 0) {
        int nz = 0;
        long long idx = 1 + 2 * ((long long)tid * (n_edges - 1) / 256);
        if (idx < 2LL * n_edges) nz = pairs_w[idx];
        int any = __syncthreads_or(nz);
        if (tid == 0) g_is64 = (any == 0) ? 1 : 0;
    }

    for (int idx = tid; idx < 3 * 2048; idx += 256) {
        int arr = idx >> 11;
        int id  = idx & 2047;
        int which = id & 1;
        int ln    = (id >> 1) & 31;
        int nt    = (id >> 6) & 7;
        int kt    = id >> 9;
        int cc = ln & 3;
        int rr = ln >> 2;
        int k0 = 16 * kt + (which ? 8 : 0) + 2 * cc;
        int n  = 8 * nt + rr;
        const float* W = (arr == 0) ? W2 : (We1 + (size_t)(arr - 1) * 4096);
        __half2 h = __floats2half2_rn(W[k0 * HID + n], W[(k0 + 1) * HID + n]);
        sFr[idx] = *(uint*)&h;
    }
    if (tid < 64)  sbias[tid] = b2[tid];
    else if (tid < 128) sbias[tid] = be1[tid - 64];

    int q = tid & 15;
    int g = tid >> 4;
    int lane = tid & 31;
    int w    = tid >> 5;
    int c = lane & 3;
    int r = lane >> 2;

    float w1r[4][4];
    #pragma unroll
    for (int cc = 0; cc < 4; cc++) {
        float4 wv = *(const float4*)&W1[cc * HID + 4 * q];
        w1r[cc][0] = wv.x; w1r[cc][1] = wv.y; w1r[cc][2] = wv.z; w1r[cc][3] = wv.w;
    }
    float4 b1r = *(const float4*)&b1[4 * q];

    uint* sW2f = sFr;
    uint* sAf  = sFr + 2048;
    uint* sBf  = sFr + 4096;
    uint shbase = smem_u32(sh);
    uint aaddr0 = shbase + (((16 * w + (lane & 15)) * ST + 4 * (lane >> 4)) << 2);
    __syncthreads();

    for (int tb = blockIdx.x * 128; tb < n_nodes; tb += gridDim.x * 128) {
        #pragma unroll
        for (int i = 0; i < 8; i++) {
            int node = tb + 8 * g + i;
            float4 x = (node < n_nodes) ? *(const float4*)&X[(size_t)node * 4]
                                        : make_float4(0.f, 0.f, 0.f, 0.f);
            float h[4];
            #pragma unroll
            for (int m = 0; m < 4; m++) {
                float hh = ((const float*)&b1r)[m];
                hh = fmaf(x.x, w1r[0][m], hh);
                hh = fmaf(x.y, w1r[1][m], hh);
                hh = fmaf(x.z, w1r[2][m], hh);
                hh = fmaf(x.w, w1r[3][m], hh);
                h[m] = fmaxf(hh, 0.f);
            }
            __half2 h01 = __floats2half2_rn(h[0], h[1]);
            __half2 h23 = __floats2half2_rn(h[2], h[3]);
            *(uint2*)&sh[(8 * g + i) * ST + 2 * q] =
                make_uint2(*(uint*)&h01, *(uint*)&h23);
        }
        __syncwarp();

        {
            float4 acc[8];
            #pragma unroll
            for (int nt = 0; nt < 8; nt++) acc[nt] = make_float4(0.f, 0.f, 0.f, 0.f);
            #pragma unroll
            for (int kt = 0; kt < 4; kt++) {
                uint a[4];
                ldm_x4(a, aaddr0 + kt * 32);
                #pragma unroll
                for (int nt = 0; nt < 8; nt++) {
                    uint2 b = *(const uint2*)&sW2f[((kt * 8 + nt) * 32 + lane) * 2];
                    mma_f16(acc[nt], a, b.x, b.y);
                }
            }
            __syncwarp();
            #pragma unroll
            for (int nt = 0; nt < 8; nt++) {
                float2 bv = *(const float2*)&sbias[8 * nt + 2 * c];
                __half2 lo = __floats2half2_rn(fmaxf(acc[nt].x + bv.x, 0.f),
                                               fmaxf(acc[nt].y + bv.y, 0.f));
                __half2 hi = __floats2half2_rn(fmaxf(acc[nt].z + bv.x, 0.f),
                                               fmaxf(acc[nt].w + bv.y, 0.f));
                sh[(16 * w + r) * ST + 4 * nt + c]     = *(uint*)&lo;
                sh[(16 * w + 8 + r) * ST + 4 * nt + c] = *(uint*)&hi;
            }
        }
        __syncwarp();

        {
            float4 pA[8], qA[8];
            #pragma unroll
            for (int nt = 0; nt < 8; nt++) {
                pA[nt] = make_float4(0.f, 0.f, 0.f, 0.f);
                qA[nt] = make_float4(0.f, 0.f, 0.f, 0.f);
            }
            #pragma unroll
            for (int kt = 0; kt < 4; kt++) {
                uint a[4];
                ldm_x4(a, aaddr0 + kt * 32);
                #pragma unroll
                for (int nt = 0; nt < 8; nt++) {
                    uint2 ba = *(const uint2*)&sAf[((kt * 8 + nt) * 32 + lane) * 2];
                    uint2 bb = *(const uint2*)&sBf[((kt * 8 + nt) * 32 + lane) * 2];
                    mma_f16(pA[nt], a, ba.x, ba.y);
                    mma_f16(qA[nt], a, bb.x, bb.y);
                }
            }
            int nodeLo = tb + 16 * w + r;
            int nodeHi = nodeLo + 8;
            #pragma unroll
            for (int nt = 0; nt < 8; nt++) {
                float2 be = *(const float2*)&sbias[64 + 8 * nt + 2 * c];
                if (nodeLo < n_nodes) {
                    __half2 p = __floats2half2_rn(pA[nt].x + be.x, pA[nt].y + be.y);
                    __half2 qq = __floats2half2_rn(qA[nt].x, qA[nt].y);
                    *(uint*)&g_Ph[(size_t)nodeLo * HID + 8 * nt + 2 * c] = *(uint*)&p;
                    *(uint*)&g_Qh[(size_t)nodeLo * HID + 8 * nt + 2 * c] = *(uint*)&qq;
                }
                if (nodeHi < n_nodes) {
                    __half2 p = __floats2half2_rn(pA[nt].z + be.x, pA[nt].w + be.y);
                    __half2 qq = __floats2half2_rn(qA[nt].z, qA[nt].w);
                    *(uint*)&g_Ph[(size_t)nodeHi * HID + 8 * nt + 2 * c] = *(uint*)&p;
                    *(uint*)&g_Qh[(size_t)nodeHi * HID + 8 * nt + 2 * c] = *(uint*)&qq;
                }
            }
        }

        #pragma unroll
        for (int it = 0; it < 4; it++) {
            int id2 = it * 32 + lane;
            int row = id2 >> 3, ch = id2 & 7;
            int node = tb + 16 * w + row;
            if (node < n_nodes)
                *(uint4*)&g_Hh[(size_t)node * HID + ch * 8] =
                    *(const uint4*)&sh[(16 * w + row) * ST + ch * 4];
        }
        __syncwarp();
    }
}

// ---------------------------------------------------------------------------
// Edge kernel v14: lane-strided index load + shfl distribution, next-tile
// index prefetch under the MMA, ldmatrix epilogue PQ reads.
// ---------------------------------------------------------------------------
__global__ __launch_bounds__(128, 4) void edge_kernel(
        const int* __restrict__ pairs,
        const float* __restrict__ We1,
        const float* __restrict__ We2,
        const float* __restrict__ be2,
        float* __restrict__ out,
        int n_edges) {
    extern __shared__ uint es14[];
    float* sW2 = (float*)es14;               // [64]
    uint*  sDall = es14 + 64;                // 4 warps x (sD[32][ST], sPQ[32][ST])

    int tid  = threadIdx.x;
    int lane = tid & 31;
    int wid  = tid >> 5;
    uint* sD  = sDall + wid * 2 * 32 * ST;
    uint* sPQ = sD + 32 * ST;

    int c = lane & 3;
    int r = lane >> 2;

    // B(C) fragments in registers, loaded once.
    const float* C = We1 + 2 * HID * HID;
    uint breg[4][8][2];
    #pragma unroll
    for (int kt = 0; kt < 4; kt++)
        #pragma unroll
        for (int nt = 0; nt < 8; nt++) {
            int n  = 8 * nt + r;
            int k0 = 16 * kt + 2 * c;
            int k1 = 16 * kt + 8 + 2 * c;
            __half2 h0 = __floats2half2_rn(C[k0 * HID + n], C[(k0 + 1) * HID + n]);
            __half2 h1 = __floats2half2_rn(C[k1 * HID + n], C[(k1 + 1) * HID + n]);
            breg[kt][nt][0] = *(uint*)&h0;
            breg[kt][nt][1] = *(uint*)&h1;
        }
    if (tid < HID) sW2[tid] = We2[tid];
    __syncthreads();

    int txg = lane & 7;
    int tyg = lane >> 3;
    float bias = be2[0];
    int is64 = g_is64;
    uint sdbase  = smem_u32(sD);
    uint spqbase = smem_u32(sPQ);
    int n_wt = (n_edges + 31) >> 5;
    int stride = gridDim.x * 4;

    int t0 = blockIdx.x * 4 + wid;

    // prologue: load this lane's edge indices for the first tile
    int2 myuv = make_int2(0, 0);
    if (t0 < n_wt) {
        long long eg = (long long)t0 * 32 + lane;
        if (eg >= n_edges) eg = n_edges - 1;
        if (is64) {
            int4 p4 = *(const int4*)&pairs[4 * eg];
            myuv = make_int2(p4.x, p4.z);
        } else {
            myuv = *(const int2*)&pairs[2 * eg];
        }
    }

    for (; t0 < n_wt; t0 += stride) {
        int ebase = t0 * 32;

        // ---- gather H diffs -> sD, P+Q -> sPQ (indices via shfl) ----
        #pragma unroll
        for (int i = 0; i < 8; i++) {
            int e  = 8 * tyg + i;
            int u = __shfl_sync(0xffffffffu, myuv.x, e);
            int v = __shfl_sync(0xffffffffu, myuv.y, e);
            uint4 hu = *(const uint4*)&g_Hh[(size_t)u * HID + 8 * txg];
            uint4 hv = *(const uint4*)&g_Hh[(size_t)v * HID + 8 * txg];
            uint4 pu = *(const uint4*)&g_Ph[(size_t)u * HID + 8 * txg];
            uint4 qv = *(const uint4*)&g_Qh[(size_t)v * HID + 8 * txg];
            uint4 d, s;
            __half2 t;
            t = __habs2(__hsub2(*(__half2*)&hu.x, *(__half2*)&hv.x)); d.x = *(uint*)&t;
            t = __habs2(__hsub2(*(__half2*)&hu.y, *(__half2*)&hv.y)); d.y = *(uint*)&t;
            t = __habs2(__hsub2(*(__half2*)&hu.z, *(__half2*)&hv.z)); d.z = *(uint*)&t;
            t = __habs2(__hsub2(*(__half2*)&hu.w, *(__half2*)&hv.w)); d.w = *(uint*)&t;
            t = __hadd2(*(__half2*)&pu.x, *(__half2*)&qv.x); s.x = *(uint*)&t;
            t = __hadd2(*(__half2*)&pu.y, *(__half2*)&qv.y); s.y = *(uint*)&t;
            t = __hadd2(*(__half2*)&pu.z, *(__half2*)&qv.z); s.z = *(uint*)&t;
            t = __hadd2(*(__half2*)&pu.w, *(__half2*)&qv.w); s.w = *(uint*)&t;
            *(uint4*)&sD[e * ST + 4 * txg]  = d;
            *(uint4*)&sPQ[e * ST + 4 * txg] = s;
        }
        __syncwarp();

        // ---- prefetch next tile's indices (latency hidden under MMA) ----
        {
            int tn = t0 + stride;
            if (tn < n_wt) {
                long long eg = (long long)tn * 32 + lane;
                if (eg >= n_edges) eg = n_edges - 1;
                if (is64) {
                    int4 p4 = *(const int4*)&pairs[4 * eg];
                    myuv = make_int2(p4.x, p4.z);
                } else {
                    myuv = *(const int2*)&pairs[2 * eg];
                }
            }
        }

        // ---- m-split: mma + epilogue per 16-edge half ----
        #pragma unroll
        for (int m = 0; m < 2; m++) {
            uint rowsel = ((16 * m + (lane & 15)) * ST + 4 * (lane >> 4)) << 2;
            float4 acc[8];
            #pragma unroll
            for (int nt = 0; nt < 8; nt++)
                acc[nt] = make_float4(0.f, 0.f, 0.f, 0.f);

            #pragma unroll
            for (int kt = 0; kt < 4; kt++) {
                uint a[4];
                ldm_x4(a, sdbase + rowsel + kt * 32);
                #pragma unroll
                for (int nt = 0; nt < 8; nt++)
                    mma_f16(acc[nt], a, breg[kt][nt][0], breg[kt][nt][1]);
            }

            // epilogue PQ via ldmatrix: pq[kt][0]=Lo(nt=2kt) [1]=Hi(2kt)
            //                           [2]=Lo(2kt+1) [3]=Hi(2kt+1)
            float sLo = 0.f, sHi = 0.f;
            #pragma unroll
            for (int kt = 0; kt < 4; kt++) {
                uint pq[4];
                ldm_x4(pq, spqbase + rowsel + kt * 32);
                #pragma unroll
                for (int h = 0; h < 2; h++) {
                    int nt = 2 * kt + h;
                    float w0 = sW2[8 * nt + 2 * c];
                    float w1 = sW2[8 * nt + 2 * c + 1];
                    float2 lo = __half22float2(*(__half2*)&pq[2 * h]);
                    float2 hi = __half22float2(*(__half2*)&pq[2 * h + 1]);
                    sLo = fmaf(fmaxf(acc[nt].x + lo.x, 0.f), w0, sLo);
                    sLo = fmaf(fmaxf(acc[nt].y + lo.y, 0.f), w1, sLo);
                    sHi = fmaf(fmaxf(acc[nt].z + hi.x, 0.f), w0, sHi);
                    sHi = fmaf(fmaxf(acc[nt].w + hi.y, 0.f), w1, sHi);
                }
            }
            sLo += __shfl_xor_sync(0xffffffffu, sLo, 1);
            sLo += __shfl_xor_sync(0xffffffffu, sLo, 2);
            sHi += __shfl_xor_sync(0xffffffffu, sHi, 1);
            sHi += __shfl_xor_sync(0xffffffffu, sHi, 2);
            if (c == 0) {
                int eLo = ebase + 16 * m + r;
                int eHi = eLo + 8;
                if (eLo < n_edges) out[eLo] = sLo + bias;
                if (eHi < n_edges) out[eHi] = sHi + bias;
            }
        }
        __syncwarp();   // all reads done before next tile overwrites sD/sPQ
    }
}

// ---------------------------------------------------------------------------
extern "C" void kernel_launch(void* const* d_in, const int* in_sizes, int n_in,
                              void* d_out, int out_size) {
    const float* X     = (const float*)d_in[0];
    const int*   pairs = (const int*)d_in[1];
    const float* W1    = (const float*)d_in[2];
    const float* b1    = (const float*)d_in[3];
    const float* W2    = (const float*)d_in[4];
    const float* b2    = (const float*)d_in[5];
    const float* We1   = (const float*)d_in[6];
    const float* be1   = (const float*)d_in[7];
    const float* We2   = (const float*)d_in[8];
    const float* be2   = (const float*)d_in[9];
    float* out = (float*)d_out;

    int n_nodes = in_sizes[0] / 4;
    int n_edges = out_size;

    cudaFuncSetAttribute(node_kernel,
                         cudaFuncAttributeMaxDynamicSharedMemorySize, NODE_SMEM);
    cudaFuncSetAttribute(edge_kernel,
                         cudaFuncAttributeMaxDynamicSharedMemorySize, EDGE_SMEM);

    node_kernel<<<296, 256, NODE_SMEM>>>(X, W1, b1, W2, b2, We1, be1,
                                         n_nodes, pairs, n_edges);
    edge_kernel<<<592, 128, EDGE_SMEM>>>(pairs, We1, We2, be2, out, n_edges);
}